// round 14
// baseline (speedup 1.0000x reference)
#include <cuda_runtime.h>
#include <cuda_bf16.h>
#include <cstdint>

#define NHEADS 5
#define BATCH  32
#define CH     512
#define NN     256
#define KCONV  4608
#define BN_EPS 1e-5f

typedef __nv_bfloat16 bf16;
typedef __nv_bfloat162 bf162;

// ---------------- scratch (device globals) ----------------
__device__ bf16 g_XTh[(size_t)NHEADS * BATCH * NN * CH];   // x transposed hi [hb][n][c]
__device__ bf16 g_XTl[(size_t)NHEADS * BATCH * NN * CH];   // lo
__device__ bf16 g_Wh[(size_t)NHEADS * CH * CH];            // V weights hi [hd][o][c]
__device__ bf16 g_Wl[(size_t)NHEADS * CH * CH];
__device__ bf16 g_WqTh[(size_t)NHEADS * CH * CH];          // Wq^T hi [hd][c][o]
__device__ bf16 g_WqTl[(size_t)NHEADS * CH * CH];
__device__ bf16 g_WkTh[(size_t)NHEADS * CH * CH];          // Wk^T hi [hd][c][o]
__device__ bf16 g_WkTl[(size_t)NHEADS * CH * CH];
__device__ bf16 g_Mh[(size_t)NHEADS * CH * CH];            // M = Wq^T Wk  [hd][c][c']
__device__ bf16 g_Ml[(size_t)NHEADS * CH * CH];
__device__ bf16 g_Kh[(size_t)NHEADS * BATCH * NN * CH];    // K'' token-major hi
__device__ bf16 g_Kl[(size_t)NHEADS * BATCH * NN * CH];
__device__ float g_PH[(size_t)NHEADS * CH * 16];           // Wq^T relH
__device__ float g_PW[(size_t)NHEADS * CH * 16];           // Wq^T relW
__device__ float g_wt[NHEADS * CH];                        // Wk^T bq
__device__ float g_dHW[NHEADS * 33];                       // bq.relH[16], bq.relW[16], bq.bk
__device__ float g_DELTA[NHEADS * BATCH * NN];             // column bias
__device__ float g_V [(size_t)NHEADS * BATCH * CH * NN];   // V channel-major fp32
__device__ float g_E [(size_t)NHEADS * BATCH * NN * NN];   // energy/attn fp32
__device__ float g_Ot[(size_t)NHEADS * BATCH * NN * CH];   // attn out token-major fp32
__device__ float g_WGT[BATCH * 4 * NN];
__device__ float g_MS[(size_t)BATCH * NN * CH];            // x_ms token-major fp32
__device__ float g_CV[(size_t)BATCH * CH * NN];            // conv out channel-major
__device__ float g_Wp[(size_t)CH * KCONV];                 // permuted conv weights fp32

// ---------------- low-level helpers ----------------
__device__ __forceinline__ uint32_t smem_u32(const void* p) {
    uint32_t a;
    asm("{ .reg .u64 t; cvta.to.shared.u64 t, %1; cvt.u32.u64 %0, t; }" : "=r"(a) : "l"(p));
    return a;
}
__device__ __forceinline__ void cpa16(uint32_t s, const void* g, int bytes) {
    asm volatile("cp.async.cg.shared.global [%0], [%1], 16, %2;" :: "r"(s), "l"(g), "r"(bytes));
}
__device__ __forceinline__ void cp_commit() { asm volatile("cp.async.commit_group;"); }
template<int N> __device__ __forceinline__ void cp_wait() {
    asm volatile("cp.async.wait_group %0;" :: "n"(N));
}
__device__ __forceinline__ uint32_t f2tf(float x) {
    uint32_t r; asm("cvt.rna.tf32.f32 %0, %1;" : "=r"(r) : "f"(x)); return r;
}
__device__ __forceinline__ void mma8(float* c, const uint32_t* a, const uint32_t* b) {
    asm volatile("mma.sync.aligned.m16n8k8.row.col.f32.tf32.tf32.f32 "
        "{%0,%1,%2,%3}, {%4,%5,%6,%7}, {%8,%9}, {%0,%1,%2,%3};"
        : "+f"(c[0]), "+f"(c[1]), "+f"(c[2]), "+f"(c[3])
        : "r"(a[0]), "r"(a[1]), "r"(a[2]), "r"(a[3]), "r"(b[0]), "r"(b[1]));
}
__device__ __forceinline__ void mma16(float* c, const uint32_t* a, const uint32_t* b) {
    asm volatile("mma.sync.aligned.m16n8k16.row.col.f32.bf16.bf16.f32 "
        "{%0,%1,%2,%3}, {%4,%5,%6,%7}, {%8,%9}, {%0,%1,%2,%3};"
        : "+f"(c[0]), "+f"(c[1]), "+f"(c[2]), "+f"(c[3])
        : "r"(a[0]), "r"(a[1]), "r"(a[2]), "r"(a[3]), "r"(b[0]), "r"(b[1]));
}
__device__ __forceinline__ bf16 bhi(float v) { return __float2bfloat16_rn(v); }
__device__ __forceinline__ bf16 blo(float v, bf16 h) {
    return __float2bfloat16_rn(v - __bfloat162float(h));
}
__device__ __forceinline__ float bf(bf16 v) { return __bfloat162float(v); }

// ================= bf16-split GEMM machinery =================
#define HSTR 40
#define HTILE (128 * HSTR)
#define HSTAGE (4 * HTILE)
#define SMEMB_BYTES (2 * HSTAGE * 2)    // 81920 B

__device__ __forceinline__ void ld_tile_h(bf16* smT, const bf16* g, int ld, int tid) {
    #pragma unroll
    for (int i = 0; i < 2; i++) {
        int idx = tid + i * 256;
        int r = idx >> 2, q = idx & 3;
        cpa16(smem_u32(smT + r * HSTR + q * 8), g + (size_t)r * ld + q * 8, 16);
    }
}

__device__ __forceinline__ void compute_chunk_bf(float cacc[4][4][4],
    const bf16* S, int wm, int wn, int lr, int lc)
{
    const bf16* Ah = S;
    const bf16* Al = S + HTILE;
    const bf16* Bh = S + 2 * HTILE;
    const bf16* Bl = S + 3 * HTILE;
    #pragma unroll
    for (int ks = 0; ks < 2; ks++) {
        int kk = ks * 16 + 2 * lc;
        uint32_t bh[4][2], bl[4][2];
        #pragma unroll
        for (int nf = 0; nf < 4; nf++) {
            int rb = (wn * 32 + nf * 8 + lr) * HSTR + kk;
            bh[nf][0] = *(const uint32_t*)(Bh + rb);
            bh[nf][1] = *(const uint32_t*)(Bh + rb + 8);
            bl[nf][0] = *(const uint32_t*)(Bl + rb);
            bl[nf][1] = *(const uint32_t*)(Bl + rb + 8);
        }
        #pragma unroll
        for (int mf = 0; mf < 4; mf++) {
            int ra = (wm * 64 + mf * 16 + lr) * HSTR + kk;
            uint32_t ah[4], al[4];
            ah[0] = *(const uint32_t*)(Ah + ra);
            ah[1] = *(const uint32_t*)(Ah + ra + 8 * HSTR);
            ah[2] = *(const uint32_t*)(Ah + ra + 8);
            ah[3] = *(const uint32_t*)(Ah + ra + 8 * HSTR + 8);
            al[0] = *(const uint32_t*)(Al + ra);
            al[1] = *(const uint32_t*)(Al + ra + 8 * HSTR);
            al[2] = *(const uint32_t*)(Al + ra + 8);
            al[3] = *(const uint32_t*)(Al + ra + 8 * HSTR + 8);
            #pragma unroll
            for (int nf = 0; nf < 4; nf++) {
                mma16(cacc[mf][nf], ah, bh[nf]);
                mma16(cacc[mf][nf], ah, bl[nf]);
                mma16(cacc[mf][nf], al, bh[nf]);
            }
        }
    }
}

__device__ __forceinline__ void run_gemm_bf(float cacc[4][4][4], bf16* sm,
    const bf16* Ah, const bf16* Al, int lda,
    const bf16* Bh, const bf16* Bl, int ldb, int nchunks, int tid)
{
    ld_tile_h(sm,             Ah, lda, tid);
    ld_tile_h(sm + HTILE,     Al, lda, tid);
    ld_tile_h(sm + 2 * HTILE, Bh, ldb, tid);
    ld_tile_h(sm + 3 * HTILE, Bl, ldb, tid);
    cp_commit();

    int wm = (tid >> 5) & 1, wn = tid >> 6, lr = (tid & 31) >> 2, lc = tid & 3;

    for (int c = 0; c < nchunks; c++) {
        if (c + 1 < nchunks) {
            bf16* d = sm + ((c + 1) & 1) * HSTAGE;
            int ko = (c + 1) * 32;
            ld_tile_h(d,             Ah + ko, lda, tid);
            ld_tile_h(d + HTILE,     Al + ko, lda, tid);
            ld_tile_h(d + 2 * HTILE, Bh + ko, ldb, tid);
            ld_tile_h(d + 3 * HTILE, Bl + ko, ldb, tid);
            cp_commit();
            cp_wait<1>();
        } else {
            cp_wait<0>();
        }
        __syncthreads();
        compute_chunk_bf(cacc, sm + (c & 1) * HSTAGE, wm, wn, lr, lc);
        __syncthreads();
    }
}

// ================= fp32/tf32 GEMM machinery (AV + conv) =================
#define ASZ (128 * 36)
#define STG (2 * ASZ)
#define SMEM_BYTES (2 * STG * 4)

__device__ __forceinline__ void ld_tile(float* smT, const float* g, int ld, int tid) {
    #pragma unroll
    for (int i = 0; i < 4; i++) {
        int idx = tid + i * 256;
        int r = idx >> 3, q = idx & 7;
        cpa16(smem_u32(smT + r * 36 + q * 4), g + (size_t)r * ld + q * 4, 16);
    }
}
__device__ __forceinline__ void ld_conv(float* smT, const float* MSb, int n0, int ch, int tid) {
    int s = ch >> 4;
    int cib = (ch & 15) * 32;
    int kh = s / 3, kw = s - kh * 3;
    #pragma unroll
    for (int i = 0; i < 4; i++) {
        int idx = tid + i * 256;
        int r = idx >> 3, q = idx & 7;
        int n = n0 + r;
        int y = (n >> 4) + kh - 1, x = (n & 15) + kw - 1;
        bool ok = ((unsigned)y < 16u) && ((unsigned)x < 16u);
        const float* src = MSb + (ok ? ((y << 4) + x) * CH : 0) + cib + q * 4;
        cpa16(smem_u32(smT + r * 36 + q * 4), src, ok ? 16 : 0);
    }
}

__device__ __forceinline__ void compute_chunk_tf(float cacc[4][4][4],
    const float* As, const float* Bs, int wm, int wn, int lr, int lc)
{
    #pragma unroll
    for (int ks = 0; ks < 4; ks++) {
        int kk = ks * 8;
        uint32_t bhv[4][2];
        #pragma unroll
        for (int nf = 0; nf < 4; nf++) {
            #pragma unroll
            for (int j = 0; j < 2; j++)
                bhv[nf][j] = f2tf(Bs[(wn * 32 + nf * 8 + lr) * 36 + kk + lc + j * 4]);
        }
        #pragma unroll
        for (int mf = 0; mf < 4; mf++) {
            uint32_t ahv[4];
            #pragma unroll
            for (int r = 0; r < 4; r++)
                ahv[r] = f2tf(As[(wm * 64 + mf * 16 + lr + (r & 1) * 8) * 36 + kk + lc + (r >> 1) * 4]);
            #pragma unroll
            for (int nf = 0; nf < 4; nf++)
                mma8(cacc[mf][nf], ahv, bhv[nf]);
        }
    }
}

template<bool CONV>
__device__ __forceinline__ void run_gemm_tf(float cacc[4][4][4], float* sm,
    const float* Aeff, int lda, const float* Beff, int ldb,
    int nchunks, const float* MSb, int n0, int tid)
{
    ld_tile(sm, Aeff, lda, tid);
    if (CONV) ld_conv(sm + ASZ, MSb, n0, 0, tid);
    else      ld_tile(sm + ASZ, Beff, ldb, tid);
    cp_commit();

    int wm = (tid >> 5) & 1, wn = tid >> 6, lr = (tid & 31) >> 2, lc = tid & 3;

    for (int c = 0; c < nchunks; c++) {
        if (c + 1 < nchunks) {
            float* d = sm + ((c + 1) & 1) * STG;
            ld_tile(d, Aeff + (c + 1) * 32, lda, tid);
            if (CONV) ld_conv(d + ASZ, MSb, n0, c + 1, tid);
            else      ld_tile(d + ASZ, Beff + (c + 1) * 32, ldb, tid);
            cp_commit();
            cp_wait<1>();
        } else {
            cp_wait<0>();
        }
        __syncthreads();
        const float* As = sm + (c & 1) * STG;
        compute_chunk_tf(cacc, As, As + ASZ, wm, wn, lr, lc);
        __syncthreads();
    }
}

// =================================================================================
// transpose x [c][n] -> XT hi/lo [hb][n][c]
// =================================================================================
__global__ void transpose_kernel(
    const float* __restrict__ x0, const float* __restrict__ x1,
    const float* __restrict__ x2, const float* __restrict__ x3,
    const float* __restrict__ x4)
{
    __shared__ float t[32][33];
    int hb = blockIdx.z, hd = hb >> 5, b = hb & 31;
    const float* X = (hd == 0 ? x0 : hd == 1 ? x1 : hd == 2 ? x2 : hd == 3 ? x3 : x4)
                     + (size_t)b * CH * NN;
    int c0 = blockIdx.y * 32, n0 = blockIdx.x * 32;
    int tx = threadIdx.x, ty = threadIdx.y;
    #pragma unroll
    for (int i = 0; i < 32; i += 8)
        t[ty + i][tx] = X[(size_t)(c0 + ty + i) * NN + n0 + tx];
    __syncthreads();
    size_t base = (size_t)hb * NN * CH;
    #pragma unroll
    for (int i = 0; i < 32; i += 8) {
        float v = t[tx][ty + i];
        bf16 h = bhi(v);
        size_t off = base + (size_t)(n0 + ty + i) * CH + c0 + tx;
        g_XTh[off] = h;
        g_XTl[off] = blo(v, h);
    }
}

// =================================================================================
// transpose-split Wq, Wk -> WqT/WkT hi/lo  [hd][c][o]
// =================================================================================
__global__ void wtrans_kernel(const float* __restrict__ qW, const float* __restrict__ kW)
{
    __shared__ float t[32][33];
    int z = blockIdx.z;
    int isK = z >= NHEADS;
    int hd = isK ? z - NHEADS : z;
    const float* W = (isK ? kW : qW) + (size_t)hd * CH * CH;
    bf16* dh = (isK ? g_WkTh : g_WqTh) + (size_t)hd * CH * CH;
    bf16* dl = (isK ? g_WkTl : g_WqTl) + (size_t)hd * CH * CH;
    int o0 = blockIdx.y * 32, c0 = blockIdx.x * 32;
    int tx = threadIdx.x, ty = threadIdx.y;
    #pragma unroll
    for (int i = 0; i < 32; i += 8)
        t[ty + i][tx] = W[(size_t)(o0 + ty + i) * CH + c0 + tx];
    __syncthreads();
    #pragma unroll
    for (int i = 0; i < 32; i += 8) {
        float v = t[tx][ty + i];
        bf16 h = bhi(v);
        size_t off = (size_t)(c0 + ty + i) * CH + o0 + tx;
        dh[off] = h;
        dl[off] = blo(v, h);
    }
}

// =================================================================================
// split V weights -> bf16 hi/lo
// =================================================================================
__global__ void wsplit_kernel(const float* __restrict__ vW)
{
    size_t i = (size_t)blockIdx.x * 256 + threadIdx.x;
    float v = vW[i];
    bf16 h = bhi(v);
    g_Wh[i] = h;
    g_Wl[i] = blo(v, h);
}

// =================================================================================
// permute conv weights
// =================================================================================
__global__ void permW_kernel(const float* __restrict__ fusW)
{
    int o = blockIdx.x;
    for (int k = threadIdx.x; k < KCONV; k += 256) {
        int s = k >> 9, ci = k & 511;
        g_Wp[(size_t)o * KCONV + k] = fusW[(size_t)o * KCONV + ci * 9 + s];
    }
}

// =================================================================================
// M = Wq^T Wk  per head (bf16 split GEMM), output split to Mh/Ml [c][c']
// =================================================================================
__global__ __launch_bounds__(256, 2) void m_mma()
{
    extern __shared__ bf16 smh[];
    int hd = blockIdx.z;
    size_t w = (size_t)hd * CH * CH;
    int rbase = blockIdx.y * 128;   // c
    int cbase = blockIdx.x * 128;   // c'
    int tid = threadIdx.x;

    float acc[4][4][4] = {};
    run_gemm_bf(acc, smh,
                g_WqTh + w + (size_t)rbase * CH, g_WqTl + w + (size_t)rbase * CH, CH,
                g_WkTh + w + (size_t)cbase * CH, g_WkTl + w + (size_t)cbase * CH, CH,
                16, tid);

    int wm = (tid >> 5) & 1, wn = tid >> 6, lr = (tid & 31) >> 2, lc = tid & 3;
    #pragma unroll
    for (int mf = 0; mf < 4; mf++) {
        #pragma unroll
        for (int nf = 0; nf < 4; nf++) {
            int cp = cbase + wn * 32 + nf * 8 + lc * 2;
            #pragma unroll
            for (int rh = 0; rh < 2; rh++) {
                int c = rbase + wm * 64 + mf * 16 + lr + rh * 8;
                float vx = acc[mf][nf][rh * 2 + 0];
                float vy = acc[mf][nf][rh * 2 + 1];
                bf16 hx = bhi(vx), hy = bhi(vy);
                size_t off = w + (size_t)c * CH + cp;
                *(bf162*)(g_Mh + off) = bf162(hx, hy);
                *(bf162*)(g_Ml + off) = bf162(blo(vx, hx), blo(vy, hy));
            }
        }
    }
}

// =================================================================================
// PH = Wq^T relH, PW = Wq^T relW  — tiled through smem.
// =================================================================================
__global__ __launch_bounds__(256) void php_kernel(
    const float* __restrict__ relH, const float* __restrict__ relW)
{
    __shared__ float sW[64][65];
    __shared__ float sR[64][33];
    int hd = blockIdx.y;
    int c0 = blockIdx.x * 64;
    int tid = threadIdx.x;
    int c = tid & 63, g = tid >> 6;
    const bf16* qh = g_WqTh + (size_t)hd * CH * CH;
    const bf16* ql = g_WqTl + (size_t)hd * CH * CH;

    float acc[8] = {};
    for (int ot = 0; ot < 8; ot++) {
        {
            int cc = tid >> 2, oo = (tid & 3) * 16;
            size_t base = (size_t)(c0 + cc) * CH + ot * 64 + oo;
            #pragma unroll
            for (int j = 0; j < 16; j++)
                sW[cc][oo + j] = bf(qh[base + j]) + bf(ql[base + j]);
        }
        {
            int oo = tid >> 2, j0 = (tid & 3) * 8;
            int og = ot * 64 + oo;
            #pragma unroll
            for (int j = 0; j < 8; j++) {
                int jj = j0 + j;
                sR[oo][jj] = (jj < 16)
                    ? relH[(size_t)(hd * CH + og) * 16 + jj]
                    : relW[(size_t)(hd * CH + og) * 16 + (jj - 16)];
            }
        }
        __syncthreads();
        #pragma unroll 8
        for (int o = 0; o < 64; o++) {
            float wv = sW[c][o];
            #pragma unroll
            for (int j = 0; j < 8; j++)
                acc[j] += wv * sR[o][g * 8 + j];
        }
        __syncthreads();
    }
    size_t idx = (size_t)(hd * CH + c0 + c) * 16;
    #pragma unroll
    for (int j = 0; j < 8; j++) {
        int jj = g * 8 + j;
        if (jj < 16) g_PH[idx + jj] = acc[j];
        else         g_PW[idx + (jj - 16)] = acc[j];
    }
}

// =================================================================================
// wt[hd][c] = Wk^T[c][:] . bq  (one warp per c)
// =================================================================================
__global__ void wt_kernel(const float* __restrict__ qB)
{
    int hd = blockIdx.y;
    int c = blockIdx.x * 8 + (threadIdx.x >> 5);
    int lane = threadIdx.x & 31;
    const bf16* kh = g_WkTh + ((size_t)hd * CH + c) * CH;
    const bf16* kl = g_WkTl + ((size_t)hd * CH + c) * CH;
    const float* bq = qB + hd * CH;
    float wt = 0.f;
    for (int o = lane; o < CH; o += 32)
        wt += (bf(kh[o]) + bf(kl[o])) * bq[o];
    #pragma unroll
    for (int off = 16; off; off >>= 1) wt += __shfl_xor_sync(0xffffffffu, wt, off);
    if (lane == 0) g_wt[hd * CH + c] = wt;
}

// =================================================================================
// dHW: bq.relH (16), bq.relW (16), bq.bk (1) per head
// =================================================================================
__global__ void dhw_kernel(const float* __restrict__ relH, const float* __restrict__ relW,
                           const float* __restrict__ qB, const float* __restrict__ kB)
{
    int hd = blockIdx.x;
    int warp = threadIdx.x >> 5, lane = threadIdx.x & 31;
    for (int j = warp; j < 33; j += 8) {
        float acc = 0.f;
        for (int o = lane; o < CH; o += 32) {
            float b = qB[hd * CH + o];
            if (j < 16)      acc += b * relH[(size_t)(hd * CH + o) * 16 + j];
            else if (j < 32) acc += b * relW[(size_t)(hd * CH + o) * 16 + (j - 16)];
            else             acc += b * kB[hd * CH + o];
        }
        #pragma unroll
        for (int off = 16; off; off >>= 1) acc += __shfl_xor_sync(0xffffffffu, acc, off);
        if (lane == 0) g_dHW[hd * 33 + j] = acc;
    }
}

// =================================================================================
// delta[hb][m] = wt . x_m + bq.pos_m + bq.bk    (warp per (hb,m))
// =================================================================================
__global__ void delta_kernel()
{
    int hb = blockIdx.y, hd = hb >> 5;
    int m = blockIdx.x * 8 + (threadIdx.x >> 5);
    int lane = threadIdx.x & 31;
    const bf16* xh = g_XTh + ((size_t)hb * NN + m) * CH;
    const bf16* xl = g_XTl + ((size_t)hb * NN + m) * CH;
    const float* wt = g_wt + hd * CH;
    float acc = 0.f;
    for (int c = lane; c < CH; c += 32)
        acc += (bf(xh[c]) + bf(xl[c])) * wt[c];
    #pragma unroll
    for (int off = 16; off; off >>= 1) acc += __shfl_xor_sync(0xffffffffu, acc, off);
    if (lane == 0)
        g_DELTA[hb * NN + m] = acc + g_dHW[hd * 33 + (m >> 4)]
                             + g_dHW[hd * 33 + 16 + (m & 15)] + g_dHW[hd * 33 + 32];
}

// =================================================================================
// K'' = Xt . M^T + Pq  (bf16 split), split-stored token-major [m][c]
// =================================================================================
__global__ __launch_bounds__(256, 2) void kpp_mma()
{
    extern __shared__ bf16 smh[];
    int hb = blockIdx.z, hd = hb >> 5;
    size_t xoff = (size_t)hb * NN * CH;
    size_t moff = (size_t)hd * CH * CH;
    int rbase = blockIdx.y * 128;   // m
    int cbase = blockIdx.x * 128;   // c
    int tid = threadIdx.x;

    float acc[4][4][4] = {};
    run_gemm_bf(acc, smh,
                g_XTh + xoff + (size_t)rbase * CH, g_XTl + xoff + (size_t)rbase * CH, CH,
                g_Mh + moff + (size_t)cbase * CH,  g_Ml + moff + (size_t)cbase * CH,  CH,
                16, tid);

    int wm = (tid >> 5) & 1, wn = tid >> 6, lr = (tid & 31) >> 2, lc = tid & 3;
    bf16* dsth = g_Kh + xoff;
    bf16* dstl = g_Kl + xoff;
    int hdC = hd * CH;
    #pragma unroll
    for (int mf = 0; mf < 4; mf++) {
        #pragma unroll
        for (int nf = 0; nf < 4; nf++) {
            int c = cbase + wn * 32 + nf * 8 + lc * 2;
            #pragma unroll
            for (int rh = 0; rh < 2; rh++) {
                int m = rbase + wm * 64 + mf * 16 + lr + rh * 8;
                int yy = m >> 4, xx = m & 15;
                float vx = acc[mf][nf][rh * 2 + 0]
                         + g_PH[(size_t)(hdC + c) * 16 + yy] + g_PW[(size_t)(hdC + c) * 16 + xx];
                float vy = acc[mf][nf][rh * 2 + 1]
                         + g_PH[(size_t)(hdC + c + 1) * 16 + yy] + g_PW[(size_t)(hdC + c + 1) * 16 + xx];
                bf16 hx = bhi(vx), hy = bhi(vy);
                size_t off = (size_t)m * CH + c;
                *(bf162*)(dsth + off) = bf162(hx, hy);
                *(bf162*)(dstl + off) = bf162(blo(vx, hx), blo(vy, hy));
            }
        }
    }
}

// =================================================================================
// V projection (bf16 split): D[o][m] = W[o][:] . Xt[m][:], fp32 out
// =================================================================================
__global__ __launch_bounds__(256, 2) void v_mma(const float* __restrict__ vB)
{
    extern __shared__ bf16 smh[];
    int hb = blockIdx.z, hd = hb >> 5;
    size_t woff = (size_t)hd * CH * CH;
    size_t xoff = (size_t)hb * NN * CH;
    int rbase = blockIdx.y * 128;   // o
    int cbase = blockIdx.x * 128;   // m
    int tid = threadIdx.x;

    float acc[4][4][4] = {};
    run_gemm_bf(acc, smh,
                g_Wh + woff + (size_t)rbase * CH,  g_Wl + woff + (size_t)rbase * CH,  CH,
                g_XTh + xoff + (size_t)cbase * CH, g_XTl + xoff + (size_t)cbase * CH, CH,
                16, tid);

    int wm = (tid >> 5) & 1, wn = tid >> 6, lr = (tid & 31) >> 2, lc = tid & 3;
    const float* bias = vB + hd * CH;
    float* dst = g_V + (size_t)hb * CH * NN;
    #pragma unroll
    for (int mf = 0; mf < 4; mf++) {
        #pragma unroll
        for (int nf = 0; nf < 4; nf++) {
            int m = cbase + wn * 32 + nf * 8 + lc * 2;
            #pragma unroll
            for (int rh = 0; rh < 2; rh++) {
                int o = rbase + wm * 64 + mf * 16 + lr + rh * 8;
                float bv = bias[o];
                *(float2*)(dst + (size_t)o * NN + m) =
                    make_float2(acc[mf][nf][rh * 2 + 0] + bv, acc[mf][nf][rh * 2 + 1] + bv);
            }
        }
    }
}

// =================================================================================
// energy (bf16 split): E[n][m] = Xt[n][:] . K''[m][:], fp32 out
// =================================================================================
__global__ __launch_bounds__(256, 2) void energy_mma()
{
    extern __shared__ bf16 smh[];
    int hb = blockIdx.z;
    size_t xoff = (size_t)hb * NN * CH;
    int rbase = blockIdx.y * 128, cbase = blockIdx.x * 128;
    int tid = threadIdx.x;

    float acc[4][4][4] = {};
    run_gemm_bf(acc, smh,
                g_XTh + xoff + (size_t)rbase * CH, g_XTl + xoff + (size_t)rbase * CH, CH,
                g_Kh + xoff + (size_t)cbase * CH,  g_Kl + xoff + (size_t)cbase * CH,  CH,
                16, tid);

    int wm = (tid >> 5) & 1, wn = tid >> 6, lr = (tid & 31) >> 2, lc = tid & 3;
    float* dst = g_E + (size_t)hb * NN * NN;
    #pragma unroll
    for (int mf = 0; mf < 4; mf++) {
        #pragma unroll
        for (int nf = 0; nf < 4; nf++) {
            int m = cbase + wn * 32 + nf * 8 + lc * 2;
            #pragma unroll
            for (int rh = 0; rh < 2; rh++) {
                int n = rbase + wm * 64 + mf * 16 + lr + rh * 8;
                *(float2*)(dst + (size_t)n * NN + m) =
                    make_float2(acc[mf][nf][rh * 2 + 0], acc[mf][nf][rh * 2 + 1]);
            }
        }
    }
}

// =================================================================================
// softmax over last dim (256) of (e + delta[m]), in place on g_E
// =================================================================================
__global__ __launch_bounds__(256) void softmax_kernel()
{
    int warp = threadIdx.x >> 5, lane = threadIdx.x & 31;
    int row = blockIdx.x * 8 + warp;
    float* e = g_E + (size_t)row * NN;
    const float* dl = g_DELTA + (size_t)(row >> 8) * NN;

    float4 a = ((float4*)e)[lane];
    float4 b = ((float4*)e)[lane + 32];
    float4 d0 = ((const float4*)dl)[lane];
    float4 d1 = ((const float4*)dl)[lane + 32];
    a.x += d0.x; a.y += d0.y; a.z += d0.z; a.w += d0.w;
    b.x += d1.x; b.y += d1.y; b.z += d1.z; b.w += d1.w;

    float m = fmaxf(fmaxf(fmaxf(a.x, a.y), fmaxf(a.z, a.w)),
                    fmaxf(fmaxf(b.x, b.y), fmaxf(b.z, b.w)));
    #pragma unroll
    for (int off = 16; off; off >>= 1) m = fmaxf(m, __shfl_xor_sync(0xffffffffu, m, off));
    a.x = __expf(a.x - m); a.y = __expf(a.y - m); a.z = __expf(a.z - m); a.w = __expf(a.w - m);
    b.x = __expf(b.x - m); b.y = __expf(b.y - m); b.z = __expf(b.z - m); b.w = __expf(b.w - m);
    float s = a.x + a.y + a.z + a.w + b.x + b.y + b.z + b.w;
    #pragma unroll
    for (int off = 16; off; off >>= 1) s += __shfl_xor_sync(0xffffffffu, s, off);
    float inv = 1.0f / s;
    a.x *= inv; a.y *= inv; a.z *= inv; a.w *= inv;
    b.x *= inv; b.y *= inv; b.z *= inv; b.w *= inv;
    ((float4*)e)[lane] = a;
    ((float4*)e)[lane + 32] = b;
}

// =================================================================================
// AV (tf32 rna): Ot[n][c] = attn[n][:] . V[c][:]
// =================================================================================
__global__ __launch_bounds__(256, 2) void av_mma()
{
    extern __shared__ float sm[];
    int hb = blockIdx.z;
    const float* A = g_E + (size_t)hb * NN * NN;
    const float* V = g_V + (size_t)hb * CH * NN;
    int rbase = blockIdx.y * 128;   // n
    int cbase = blockIdx.x * 128;   // c
    int tid = threadIdx.x;

    float acc[4][4][4] = {};
    run_gemm_tf<false>(acc, sm, A + (size_t)rbase * NN, NN,
                       V + (size_t)cbase * NN, NN, 8, nullptr, 0, tid);

    int wm = (tid >> 5) & 1, wn = tid >> 6, lr = (tid & 31) >> 2, lc = tid & 3;
    float* dst = g_Ot + (size_t)hb * NN * CH;
    #pragma unroll
    for (int mf = 0; mf < 4; mf++) {
        #pragma unroll
        for (int nf = 0; nf < 4; nf++) {
            int c = cbase + wn * 32 + nf * 8 + lc * 2;
            #pragma unroll
            for (int rh = 0; rh < 2; rh++) {
                int n = rbase + wm * 64 + mf * 16 + lr + rh * 8;
                *(float2*)(dst + (size_t)n * CH + c) =
                    make_float2(acc[mf][nf][rh * 2 + 0], acc[mf][nf][rh * 2 + 1]);
            }
        }
    }
}

// =================================================================================
// msw gating: one warp per (b, n)
// =================================================================================
__global__ __launch_bounds__(256) void msw_kernel(
    const float* __restrict__ mswW, const float* __restrict__ gg,
    const float* __restrict__ bbt,  const float* __restrict__ mmn,
    const float* __restrict__ vvr)
{
    int b = blockIdx.y;
    int n = blockIdx.x * 8 + (threadIdx.x >> 5);
    int lane = threadIdx.x & 31;
    float a0 = 0.f, a1 = 0.f, a2 = 0.f, a3 = 0.f;
    #pragma unroll
    for (int hd = 0; hd < NHEADS; hd++) {
        const float* base = g_Ot + ((size_t)(hd * BATCH + b) * NN + n) * CH;
        const float* w = mswW + hd * CH;
        for (int c = lane; c < CH; c += 32) {
            float xv = base[c];
            a0 += xv * w[c];
            a1 += xv * w[2560 + c];
            a2 += xv * w[2 * 2560 + c];
            a3 += xv * w[3 * 2560 + c];
        }
    }
    #pragma unroll
    for (int off = 16; off; off >>= 1) {
        a0 += __shfl_xor_sync(0xffffffffu, a0, off);
        a1 += __shfl_xor_sync(0xffffffffu, a1, off);
        a2 += __shfl_xor_sync(0xffffffffu, a2, off);
        a3 += __shfl_xor_sync(0xffffffffu, a3, off);
    }
    if (lane < 4) {
        float acc = lane == 0 ? a0 : lane == 1 ? a1 : lane == 2 ? a2 : a3;
        float z = (acc - mmn[lane]) * (gg[lane] * rsqrtf(vvr[lane] + BN_EPS)) + bbt[lane];
        g_WGT[(b * 4 + lane) * NN + n] = 1.f / (1.f + __expf(-z));
    }
}

// =================================================================================
// combine: x_ms[b][n][c] = Ot4 + sum_i w_i[n] * Ot_i
// =================================================================================
__global__ __launch_bounds__(256) void combine_kernel()
{
    int idx = blockIdx.x * 256 + threadIdx.x;
    int b = idx >> 17;
    int n = (idx >> 9) & 255;
    const float* w = g_WGT + b * 4 * NN;
    size_t hs = (size_t)BATCH * NN * CH;
    size_t off = (size_t)idx;
    float r = g_Ot[4 * hs + off]
            + w[n]          * g_Ot[off]
            + w[NN + n]     * g_Ot[hs + off]
            + w[2 * NN + n] * g_Ot[2 * hs + off]
            + w[3 * NN + n] * g_Ot[3 * hs + off];
    g_MS[off] = r;
}

// =================================================================================
// conv3x3 implicit GEMM (tf32 rna): D[o][n], K = 4608
// =================================================================================
__global__ __launch_bounds__(256, 2) void conv_mma()
{
    extern __shared__ float sm[];
    int b = blockIdx.z;
    int rbase = blockIdx.y * 128;   // o
    int cbase = blockIdx.x * 128;   // n
    const float* MSb = g_MS + (size_t)b * NN * CH;
    int tid = threadIdx.x;

    float acc[4][4][4] = {};
    run_gemm_tf<true>(acc, sm, g_Wp + (size_t)rbase * KCONV, KCONV,
                      nullptr, 0, 144, MSb, cbase, tid);

    int wm = (tid >> 5) & 1, wn = tid >> 6, lr = (tid & 31) >> 2, lc = tid & 3;
    float* dst = g_CV + (size_t)b * CH * NN;
    #pragma unroll
    for (int mf = 0; mf < 4; mf++) {
        #pragma unroll
        for (int nf = 0; nf < 4; nf++) {
            int n = cbase + wn * 32 + nf * 8 + lc * 2;
            #pragma unroll
            for (int rh = 0; rh < 2; rh++) {
                int o = rbase + wm * 64 + mf * 16 + lr + rh * 8;
                *(float2*)(dst + (size_t)o * NN + n) =
                    make_float2(acc[mf][nf][rh * 2 + 0], acc[mf][nf][rh * 2 + 1]);
            }
        }
    }
}

// =================================================================================
// final: out = relu(bn_top(relu(bn_fus(conv)) + x))
// =================================================================================
__global__ __launch_bounds__(256) void final_kernel(
    const float* __restrict__ x,
    const float* __restrict__ fg, const float* __restrict__ fb,
    const float* __restrict__ fm, const float* __restrict__ fv,
    const float* __restrict__ tg, const float* __restrict__ tb,
    const float* __restrict__ tm, const float* __restrict__ tv,
    float* __restrict__ out)
{
    int idx = blockIdx.x * 256 + threadIdx.x;
    int c = (idx >> 8) & 511;
    float t = g_CV[idx];
    t = (t - fm[c]) * (fg[c] * rsqrtf(fv[c] + BN_EPS)) + fb[c];
    t = fmaxf(t, 0.f);
    t += x[idx];
    t = (t - tm[c]) * (tg[c] * rsqrtf(tv[c] + BN_EPS)) + tb[c];
    out[idx] = fmaxf(t, 0.f);
}

// =================================================================================
extern "C" void kernel_launch(void* const* d_in, const int* in_sizes, int n_in,
                              void* d_out, int out_size)
{
    const float* x0   = (const float*)d_in[0];
    const float* x1   = (const float*)d_in[1];
    const float* x2   = (const float*)d_in[2];
    const float* x3   = (const float*)d_in[3];
    const float* x4   = (const float*)d_in[4];
    const float* qW   = (const float*)d_in[5];
    const float* qB   = (const float*)d_in[6];
    const float* kW   = (const float*)d_in[7];
    const float* kB   = (const float*)d_in[8];
    const float* vW   = (const float*)d_in[9];
    const float* vB   = (const float*)d_in[10];
    const float* relH = (const float*)d_in[11];
    const float* relW = (const float*)d_in[12];
    const float* mswW = (const float*)d_in[13];
    const float* mswg = (const float*)d_in[14];
    const float* mswb = (const float*)d_in[15];
    const float* mswm = (const float*)d_in[16];
    const float* mswv = (const float*)d_in[17];
    const float* fusW = (const float*)d_in[18];
    const float* fusg = (const float*)d_in[19];
    const float* fusb = (const float*)d_in[20];
    const float* fusm = (const float*)d_in[21];
    const float* fusv = (const float*)d_in[22];
    const float* topg = (const float*)d_in[23];
    const float* topb = (const float*)d_in[24];
    const float* topm = (const float*)d_in[25];
    const float* topv = (const float*)d_in[26];
    float* out = (float*)d_out;

    cudaFuncSetAttribute(m_mma,      cudaFuncAttributeMaxDynamicSharedMemorySize, SMEMB_BYTES);
    cudaFuncSetAttribute(kpp_mma,    cudaFuncAttributeMaxDynamicSharedMemorySize, SMEMB_BYTES);
    cudaFuncSetAttribute(v_mma,      cudaFuncAttributeMaxDynamicSharedMemorySize, SMEMB_BYTES);
    cudaFuncSetAttribute(energy_mma, cudaFuncAttributeMaxDynamicSharedMemorySize, SMEMB_BYTES);
    cudaFuncSetAttribute(av_mma,     cudaFuncAttributeMaxDynamicSharedMemorySize, SMEM_BYTES);
    cudaFuncSetAttribute(conv_mma,   cudaFuncAttributeMaxDynamicSharedMemorySize, SMEM_BYTES);

    // Two-stream fork/join: s1 runs the (under-occupied) prep + K''/energy/softmax
    // chain; s0 runs transpose + V-projection concurrently, joining before AV.
    // Stream/events are created per call and intentionally never destroyed
    // (host-side objects only, a handful of calls total; destroying a captured
    // stream during graph capture is illegal).
    cudaStream_t s1;
    cudaStreamCreateWithFlags(&s1, cudaStreamNonBlocking);
    cudaEvent_t evFork, evXT, evJoin;
    cudaEventCreateWithFlags(&evFork, cudaEventDisableTiming);
    cudaEventCreateWithFlags(&evXT,   cudaEventDisableTiming);
    cudaEventCreateWithFlags(&evJoin, cudaEventDisableTiming);

    // fork
    cudaEventRecord(evFork, 0);
    cudaStreamWaitEvent(s1, evFork, 0);

    // ---- s1: weight-side prep chain (no XT dependency yet) ----
    wtrans_kernel<<<dim3(16, 16, 2 * NHEADS), dim3(32, 8), 0, s1>>>(qW, kW);
    m_mma<<<dim3(4, 4, NHEADS), 256, SMEMB_BYTES, s1>>>();
    php_kernel<<<dim3(CH / 64, NHEADS), 256, 0, s1>>>(relH, relW);
    wt_kernel<<<dim3(CH / 8, NHEADS), 256, 0, s1>>>(qB);
    dhw_kernel<<<NHEADS, 256, 0, s1>>>(relH, relW, qB, kB);

    // ---- s0: input transpose + V weight split + conv weight permute ----
    transpose_kernel<<<dim3(8, 16, NHEADS * BATCH), dim3(32, 8)>>>(x0, x1, x2, x3, x4);
    wsplit_kernel<<<NHEADS * CH * CH / 256, 256>>>(vW);
    permW_kernel<<<CH, 256>>>(fusW);
    cudaEventRecord(evXT, 0);

    // ---- s0: V projection runs concurrently with s1's K'' chain ----
    v_mma<<<dim3(2, 4, NHEADS * BATCH), 256, SMEMB_BYTES>>>(vB);

    // ---- s1: XT-dependent chain ----
    cudaStreamWaitEvent(s1, evXT, 0);
    delta_kernel<<<dim3(NN / 8, NHEADS * BATCH), 256, 0, s1>>>();
    kpp_mma<<<dim3(4, 2, NHEADS * BATCH), 256, SMEMB_BYTES, s1>>>();
    energy_mma<<<dim3(2, 2, NHEADS * BATCH), 256, SMEMB_BYTES, s1>>>();
    softmax_kernel<<<(NHEADS * BATCH * NN) / 8, 256, 0, s1>>>();
    cudaEventRecord(evJoin, s1);

    // ---- s0: join, then attention output + tail ----
    cudaStreamWaitEvent(0, evJoin, 0);
    av_mma<<<dim3(4, 2, NHEADS * BATCH), 256, SMEM_BYTES>>>();

    msw_kernel<<<dim3(NN / 8, BATCH), 256>>>(mswW, mswg, mswb, mswm, mswv);
    combine_kernel<<<(BATCH * NN * CH) / 256, 256>>>();

    conv_mma<<<dim3(2, 4, BATCH), 256, SMEM_BYTES>>>();

    final_kernel<<<(BATCH * CH * NN) / 256, 256>>>(
        x4, fusg, fusb, fusm, fusv, topg, topb, topm, topv, out);
}

// round 15
// speedup vs baseline: 1.1378x; 1.1378x over previous
#include <cuda_runtime.h>
#include <cuda_bf16.h>
#include <cstdint>

#define NHEADS 5
#define BATCH  32
#define CH     512
#define NN     256
#define KCONV  4608
#define BN_EPS 1e-5f

typedef __nv_bfloat16 bf16;
typedef __nv_bfloat162 bf162;

// ---------------- scratch (device globals) ----------------
__device__ bf16 g_XTh[(size_t)NHEADS * BATCH * NN * CH];   // x transposed hi [hb][n][c]
__device__ bf16 g_XTl[(size_t)NHEADS * BATCH * NN * CH];   // lo
__device__ bf16 g_Wh[(size_t)NHEADS * CH * CH];            // V weights hi [hd][o][c]
__device__ bf16 g_Wl[(size_t)NHEADS * CH * CH];
__device__ bf16 g_WqTh[(size_t)NHEADS * CH * CH];          // Wq^T hi [hd][c][o]
__device__ bf16 g_WqTl[(size_t)NHEADS * CH * CH];
__device__ bf16 g_WkTh[(size_t)NHEADS * CH * CH];          // Wk^T hi [hd][c][o]
__device__ bf16 g_WkTl[(size_t)NHEADS * CH * CH];
__device__ bf16 g_Mh[(size_t)NHEADS * CH * CH];            // M = Wq^T Wk  [hd][c][c']
__device__ bf16 g_Ml[(size_t)NHEADS * CH * CH];
__device__ bf16 g_Kh[(size_t)NHEADS * BATCH * NN * CH];    // K'' token-major hi
__device__ bf16 g_Kl[(size_t)NHEADS * BATCH * NN * CH];
__device__ float g_PH[(size_t)NHEADS * CH * 16];           // Wq^T relH
__device__ float g_PW[(size_t)NHEADS * CH * 16];           // Wq^T relW
__device__ float g_wt[NHEADS * CH];                        // Wk^T bq
__device__ float g_dHW[NHEADS * 33];                       // bq.relH[16], bq.relW[16], bq.bk
__device__ float g_DELTA[NHEADS * BATCH * NN];             // column bias
__device__ float g_V [(size_t)NHEADS * BATCH * CH * NN];   // V channel-major, tf32-rounded
__device__ float g_E [(size_t)NHEADS * BATCH * NN * NN];   // energy -> attn (tf32-rounded)
__device__ float g_Ot[(size_t)NHEADS * BATCH * NN * CH];   // attn out token-major fp32
__device__ float g_WGT[BATCH * 4 * NN];
__device__ float g_MS[(size_t)BATCH * NN * CH];            // x_ms token-major, tf32-rounded
__device__ float g_CV[(size_t)BATCH * CH * NN];            // conv out channel-major
__device__ float g_Wp[(size_t)CH * KCONV];                 // permuted conv weights, tf32-rounded

// ---------------- low-level helpers ----------------
__device__ __forceinline__ uint32_t smem_u32(const void* p) {
    uint32_t a;
    asm("{ .reg .u64 t; cvta.to.shared.u64 t, %1; cvt.u32.u64 %0, t; }" : "=r"(a) : "l"(p));
    return a;
}
__device__ __forceinline__ void cpa16(uint32_t s, const void* g, int bytes) {
    asm volatile("cp.async.cg.shared.global [%0], [%1], 16, %2;" :: "r"(s), "l"(g), "r"(bytes));
}
__device__ __forceinline__ void cp_commit() { asm volatile("cp.async.commit_group;"); }
template<int N> __device__ __forceinline__ void cp_wait() {
    asm volatile("cp.async.wait_group %0;" :: "n"(N));
}
__device__ __forceinline__ uint32_t f2tf(float x) {
    uint32_t r; asm("cvt.rna.tf32.f32 %0, %1;" : "=r"(r) : "f"(x)); return r;
}
__device__ __forceinline__ float tfround(float x) { return __uint_as_float(f2tf(x)); }
__device__ __forceinline__ void mma8(float* c, const uint32_t* a, const uint32_t* b) {
    asm volatile("mma.sync.aligned.m16n8k8.row.col.f32.tf32.tf32.f32 "
        "{%0,%1,%2,%3}, {%4,%5,%6,%7}, {%8,%9}, {%0,%1,%2,%3};"
        : "+f"(c[0]), "+f"(c[1]), "+f"(c[2]), "+f"(c[3])
        : "r"(a[0]), "r"(a[1]), "r"(a[2]), "r"(a[3]), "r"(b[0]), "r"(b[1]));
}
__device__ __forceinline__ void mma16(float* c, const uint32_t* a, const uint32_t* b) {
    asm volatile("mma.sync.aligned.m16n8k16.row.col.f32.bf16.bf16.f32 "
        "{%0,%1,%2,%3}, {%4,%5,%6,%7}, {%8,%9}, {%0,%1,%2,%3};"
        : "+f"(c[0]), "+f"(c[1]), "+f"(c[2]), "+f"(c[3])
        : "r"(a[0]), "r"(a[1]), "r"(a[2]), "r"(a[3]), "r"(b[0]), "r"(b[1]));
}
__device__ __forceinline__ bf16 bhi(float v) { return __float2bfloat16_rn(v); }
__device__ __forceinline__ bf16 blo(float v, bf16 h) {
    return __float2bfloat16_rn(v - __bfloat162float(h));
}
__device__ __forceinline__ float bf(bf16 v) { return __bfloat162float(v); }

// ================= bf16-split GEMM machinery =================
#define HSTR 40
#define HTILE (128 * HSTR)
#define HSTAGE (4 * HTILE)
#define SMEMB_BYTES (2 * HSTAGE * 2)    // 81920 B

__device__ __forceinline__ void ld_tile_h(bf16* smT, const bf16* g, int ld, int tid) {
    #pragma unroll
    for (int i = 0; i < 2; i++) {
        int idx = tid + i * 256;
        int r = idx >> 2, q = idx & 3;
        cpa16(smem_u32(smT + r * HSTR + q * 8), g + (size_t)r * ld + q * 8, 16);
    }
}

__device__ __forceinline__ void compute_chunk_bf(float cacc[4][4][4],
    const bf16* S, int wm, int wn, int lr, int lc)
{
    const bf16* Ah = S;
    const bf16* Al = S + HTILE;
    const bf16* Bh = S + 2 * HTILE;
    const bf16* Bl = S + 3 * HTILE;
    #pragma unroll
    for (int ks = 0; ks < 2; ks++) {
        int kk = ks * 16 + 2 * lc;
        uint32_t bh[4][2], bl[4][2];
        #pragma unroll
        for (int nf = 0; nf < 4; nf++) {
            int rb = (wn * 32 + nf * 8 + lr) * HSTR + kk;
            bh[nf][0] = *(const uint32_t*)(Bh + rb);
            bh[nf][1] = *(const uint32_t*)(Bh + rb + 8);
            bl[nf][0] = *(const uint32_t*)(Bl + rb);
            bl[nf][1] = *(const uint32_t*)(Bl + rb + 8);
        }
        #pragma unroll
        for (int mf = 0; mf < 4; mf++) {
            int ra = (wm * 64 + mf * 16 + lr) * HSTR + kk;
            uint32_t ah[4], al[4];
            ah[0] = *(const uint32_t*)(Ah + ra);
            ah[1] = *(const uint32_t*)(Ah + ra + 8 * HSTR);
            ah[2] = *(const uint32_t*)(Ah + ra + 8);
            ah[3] = *(const uint32_t*)(Ah + ra + 8 * HSTR + 8);
            al[0] = *(const uint32_t*)(Al + ra);
            al[1] = *(const uint32_t*)(Al + ra + 8 * HSTR);
            al[2] = *(const uint32_t*)(Al + ra + 8);
            al[3] = *(const uint32_t*)(Al + ra + 8 * HSTR + 8);
            #pragma unroll
            for (int nf = 0; nf < 4; nf++) {
                mma16(cacc[mf][nf], ah, bh[nf]);
                mma16(cacc[mf][nf], ah, bl[nf]);
                mma16(cacc[mf][nf], al, bh[nf]);
            }
        }
    }
}

__device__ __forceinline__ void run_gemm_bf(float cacc[4][4][4], bf16* sm,
    const bf16* Ah, const bf16* Al, int lda,
    const bf16* Bh, const bf16* Bl, int ldb, int nchunks, int tid)
{
    ld_tile_h(sm,             Ah, lda, tid);
    ld_tile_h(sm + HTILE,     Al, lda, tid);
    ld_tile_h(sm + 2 * HTILE, Bh, ldb, tid);
    ld_tile_h(sm + 3 * HTILE, Bl, ldb, tid);
    cp_commit();

    int wm = (tid >> 5) & 1, wn = tid >> 6, lr = (tid & 31) >> 2, lc = tid & 3;

    for (int c = 0; c < nchunks; c++) {
        if (c + 1 < nchunks) {
            bf16* d = sm + ((c + 1) & 1) * HSTAGE;
            int ko = (c + 1) * 32;
            ld_tile_h(d,             Ah + ko, lda, tid);
            ld_tile_h(d + HTILE,     Al + ko, lda, tid);
            ld_tile_h(d + 2 * HTILE, Bh + ko, ldb, tid);
            ld_tile_h(d + 3 * HTILE, Bl + ko, ldb, tid);
            cp_commit();
            cp_wait<1>();
        } else {
            cp_wait<0>();
        }
        __syncthreads();
        compute_chunk_bf(cacc, sm + (c & 1) * HSTAGE, wm, wn, lr, lc);
        __syncthreads();
    }
}

// ================= tf32 GEMM machinery (AV + conv); operands pre-rounded =================
#define ASZ (128 * 36)
#define STG (2 * ASZ)
#define SMEM_BYTES (2 * STG * 4)

__device__ __forceinline__ void ld_tile(float* smT, const float* g, int ld, int tid) {
    #pragma unroll
    for (int i = 0; i < 4; i++) {
        int idx = tid + i * 256;
        int r = idx >> 3, q = idx & 7;
        cpa16(smem_u32(smT + r * 36 + q * 4), g + (size_t)r * ld + q * 4, 16);
    }
}
__device__ __forceinline__ void ld_conv(float* smT, const float* MSb, int n0, int ch, int tid) {
    int s = ch >> 4;
    int cib = (ch & 15) * 32;
    int kh = s / 3, kw = s - kh * 3;
    #pragma unroll
    for (int i = 0; i < 4; i++) {
        int idx = tid + i * 256;
        int r = idx >> 3, q = idx & 7;
        int n = n0 + r;
        int y = (n >> 4) + kh - 1, x = (n & 15) + kw - 1;
        bool ok = ((unsigned)y < 16u) && ((unsigned)x < 16u);
        const float* src = MSb + (ok ? ((y << 4) + x) * CH : 0) + cib + q * 4;
        cpa16(smem_u32(smT + r * 36 + q * 4), src, ok ? 16 : 0);
    }
}

// operands in smem are already tf32-rounded fp32 — pass raw bits, no cvt.
__device__ __forceinline__ void compute_chunk_tf(float cacc[4][4][4],
    const float* As, const float* Bs, int wm, int wn, int lr, int lc)
{
    #pragma unroll
    for (int ks = 0; ks < 4; ks++) {
        int kk = ks * 8;
        uint32_t bhv[4][2];
        #pragma unroll
        for (int nf = 0; nf < 4; nf++) {
            #pragma unroll
            for (int j = 0; j < 2; j++)
                bhv[nf][j] = __float_as_uint(Bs[(wn * 32 + nf * 8 + lr) * 36 + kk + lc + j * 4]);
        }
        #pragma unroll
        for (int mf = 0; mf < 4; mf++) {
            uint32_t ahv[4];
            #pragma unroll
            for (int r = 0; r < 4; r++)
                ahv[r] = __float_as_uint(As[(wm * 64 + mf * 16 + lr + (r & 1) * 8) * 36 + kk + lc + (r >> 1) * 4]);
            #pragma unroll
            for (int nf = 0; nf < 4; nf++)
                mma8(cacc[mf][nf], ahv, bhv[nf]);
        }
    }
}

template<bool CONV>
__device__ __forceinline__ void run_gemm_tf(float cacc[4][4][4], float* sm,
    const float* Aeff, int lda, const float* Beff, int ldb,
    int nchunks, const float* MSb, int n0, int tid)
{
    ld_tile(sm, Aeff, lda, tid);
    if (CONV) ld_conv(sm + ASZ, MSb, n0, 0, tid);
    else      ld_tile(sm + ASZ, Beff, ldb, tid);
    cp_commit();

    int wm = (tid >> 5) & 1, wn = tid >> 6, lr = (tid & 31) >> 2, lc = tid & 3;

    for (int c = 0; c < nchunks; c++) {
        if (c + 1 < nchunks) {
            float* d = sm + ((c + 1) & 1) * STG;
            ld_tile(d, Aeff + (c + 1) * 32, lda, tid);
            if (CONV) ld_conv(d + ASZ, MSb, n0, c + 1, tid);
            else      ld_tile(d + ASZ, Beff + (c + 1) * 32, ldb, tid);
            cp_commit();
            cp_wait<1>();
        } else {
            cp_wait<0>();
        }
        __syncthreads();
        const float* As = sm + (c & 1) * STG;
        compute_chunk_tf(cacc, As, As + ASZ, wm, wn, lr, lc);
        __syncthreads();
    }
}

// =================================================================================
// transpose x [c][n] -> XT hi/lo [hb][n][c]
// =================================================================================
__global__ void transpose_kernel(
    const float* __restrict__ x0, const float* __restrict__ x1,
    const float* __restrict__ x2, const float* __restrict__ x3,
    const float* __restrict__ x4)
{
    __shared__ float t[32][33];
    int hb = blockIdx.z, hd = hb >> 5, b = hb & 31;
    const float* X = (hd == 0 ? x0 : hd == 1 ? x1 : hd == 2 ? x2 : hd == 3 ? x3 : x4)
                     + (size_t)b * CH * NN;
    int c0 = blockIdx.y * 32, n0 = blockIdx.x * 32;
    int tx = threadIdx.x, ty = threadIdx.y;
    #pragma unroll
    for (int i = 0; i < 32; i += 8)
        t[ty + i][tx] = X[(size_t)(c0 + ty + i) * NN + n0 + tx];
    __syncthreads();
    size_t base = (size_t)hb * NN * CH;
    #pragma unroll
    for (int i = 0; i < 32; i += 8) {
        float v = t[tx][ty + i];
        bf16 h = bhi(v);
        size_t off = base + (size_t)(n0 + ty + i) * CH + c0 + tx;
        g_XTh[off] = h;
        g_XTl[off] = blo(v, h);
    }
}

// =================================================================================
// transpose-split Wq, Wk -> WqT/WkT hi/lo  [hd][c][o]
// =================================================================================
__global__ void wtrans_kernel(const float* __restrict__ qW, const float* __restrict__ kW)
{
    __shared__ float t[32][33];
    int z = blockIdx.z;
    int isK = z >= NHEADS;
    int hd = isK ? z - NHEADS : z;
    const float* W = (isK ? kW : qW) + (size_t)hd * CH * CH;
    bf16* dh = (isK ? g_WkTh : g_WqTh) + (size_t)hd * CH * CH;
    bf16* dl = (isK ? g_WkTl : g_WqTl) + (size_t)hd * CH * CH;
    int o0 = blockIdx.y * 32, c0 = blockIdx.x * 32;
    int tx = threadIdx.x, ty = threadIdx.y;
    #pragma unroll
    for (int i = 0; i < 32; i += 8)
        t[ty + i][tx] = W[(size_t)(o0 + ty + i) * CH + c0 + tx];
    __syncthreads();
    #pragma unroll
    for (int i = 0; i < 32; i += 8) {
        float v = t[tx][ty + i];
        bf16 h = bhi(v);
        size_t off = (size_t)(c0 + ty + i) * CH + o0 + tx;
        dh[off] = h;
        dl[off] = blo(v, h);
    }
}

// =================================================================================
// split V weights -> bf16 hi/lo
// =================================================================================
__global__ void wsplit_kernel(const float* __restrict__ vW)
{
    size_t i = (size_t)blockIdx.x * 256 + threadIdx.x;
    float v = vW[i];
    bf16 h = bhi(v);
    g_Wh[i] = h;
    g_Wl[i] = blo(v, h);
}

// =================================================================================
// permute conv weights (tf32-rounded at store)
// =================================================================================
__global__ void permW_kernel(const float* __restrict__ fusW)
{
    int o = blockIdx.x;
    for (int k = threadIdx.x; k < KCONV; k += 256) {
        int s = k >> 9, ci = k & 511;
        g_Wp[(size_t)o * KCONV + k] = tfround(fusW[(size_t)o * KCONV + ci * 9 + s]);
    }
}

// =================================================================================
// M = Wq^T Wk  per head (bf16 split GEMM), output split to Mh/Ml [c][c']
// =================================================================================
__global__ __launch_bounds__(256, 2) void m_mma()
{
    extern __shared__ bf16 smh[];
    int hd = blockIdx.z;
    size_t w = (size_t)hd * CH * CH;
    int rbase = blockIdx.y * 128;   // c
    int cbase = blockIdx.x * 128;   // c'
    int tid = threadIdx.x;

    float acc[4][4][4] = {};
    run_gemm_bf(acc, smh,
                g_WqTh + w + (size_t)rbase * CH, g_WqTl + w + (size_t)rbase * CH, CH,
                g_WkTh + w + (size_t)cbase * CH, g_WkTl + w + (size_t)cbase * CH, CH,
                16, tid);

    int wm = (tid >> 5) & 1, wn = tid >> 6, lr = (tid & 31) >> 2, lc = tid & 3;
    #pragma unroll
    for (int mf = 0; mf < 4; mf++) {
        #pragma unroll
        for (int nf = 0; nf < 4; nf++) {
            int cp = cbase + wn * 32 + nf * 8 + lc * 2;
            #pragma unroll
            for (int rh = 0; rh < 2; rh++) {
                int c = rbase + wm * 64 + mf * 16 + lr + rh * 8;
                float vx = acc[mf][nf][rh * 2 + 0];
                float vy = acc[mf][nf][rh * 2 + 1];
                bf16 hx = bhi(vx), hy = bhi(vy);
                size_t off = w + (size_t)c * CH + cp;
                *(bf162*)(g_Mh + off) = bf162(hx, hy);
                *(bf162*)(g_Ml + off) = bf162(blo(vx, hx), blo(vy, hy));
            }
        }
    }
}

// =================================================================================
// PH = Wq^T relH, PW = Wq^T relW  — tiled through smem.
// =================================================================================
__global__ __launch_bounds__(256) void php_kernel(
    const float* __restrict__ relH, const float* __restrict__ relW)
{
    __shared__ float sW[64][65];
    __shared__ float sR[64][33];
    int hd = blockIdx.y;
    int c0 = blockIdx.x * 64;
    int tid = threadIdx.x;
    int c = tid & 63, g = tid >> 6;
    const bf16* qh = g_WqTh + (size_t)hd * CH * CH;
    const bf16* ql = g_WqTl + (size_t)hd * CH * CH;

    float acc[8] = {};
    for (int ot = 0; ot < 8; ot++) {
        {
            int cc = tid >> 2, oo = (tid & 3) * 16;
            size_t base = (size_t)(c0 + cc) * CH + ot * 64 + oo;
            #pragma unroll
            for (int j = 0; j < 16; j++)
                sW[cc][oo + j] = bf(qh[base + j]) + bf(ql[base + j]);
        }
        {
            int oo = tid >> 2, j0 = (tid & 3) * 8;
            int og = ot * 64 + oo;
            #pragma unroll
            for (int j = 0; j < 8; j++) {
                int jj = j0 + j;
                sR[oo][jj] = (jj < 16)
                    ? relH[(size_t)(hd * CH + og) * 16 + jj]
                    : relW[(size_t)(hd * CH + og) * 16 + (jj - 16)];
            }
        }
        __syncthreads();
        #pragma unroll 8
        for (int o = 0; o < 64; o++) {
            float wv = sW[c][o];
            #pragma unroll
            for (int j = 0; j < 8; j++)
                acc[j] += wv * sR[o][g * 8 + j];
        }
        __syncthreads();
    }
    size_t idx = (size_t)(hd * CH + c0 + c) * 16;
    #pragma unroll
    for (int j = 0; j < 8; j++) {
        int jj = g * 8 + j;
        if (jj < 16) g_PH[idx + jj] = acc[j];
        else         g_PW[idx + (jj - 16)] = acc[j];
    }
}

// =================================================================================
// wt[hd][c] = Wk^T[c][:] . bq  (one warp per c)
// =================================================================================
__global__ void wt_kernel(const float* __restrict__ qB)
{
    int hd = blockIdx.y;
    int c = blockIdx.x * 8 + (threadIdx.x >> 5);
    int lane = threadIdx.x & 31;
    const bf16* kh = g_WkTh + ((size_t)hd * CH + c) * CH;
    const bf16* kl = g_WkTl + ((size_t)hd * CH + c) * CH;
    const float* bq = qB + hd * CH;
    float wt = 0.f;
    for (int o = lane; o < CH; o += 32)
        wt += (bf(kh[o]) + bf(kl[o])) * bq[o];
    #pragma unroll
    for (int off = 16; off; off >>= 1) wt += __shfl_xor_sync(0xffffffffu, wt, off);
    if (lane == 0) g_wt[hd * CH + c] = wt;
}

// =================================================================================
// dHW: bq.relH (16), bq.relW (16), bq.bk (1) per head
// =================================================================================
__global__ void dhw_kernel(const float* __restrict__ relH, const float* __restrict__ relW,
                           const float* __restrict__ qB, const float* __restrict__ kB)
{
    int hd = blockIdx.x;
    int warp = threadIdx.x >> 5, lane = threadIdx.x & 31;
    for (int j = warp; j < 33; j += 8) {
        float acc = 0.f;
        for (int o = lane; o < CH; o += 32) {
            float b = qB[hd * CH + o];
            if (j < 16)      acc += b * relH[(size_t)(hd * CH + o) * 16 + j];
            else if (j < 32) acc += b * relW[(size_t)(hd * CH + o) * 16 + (j - 16)];
            else             acc += b * kB[hd * CH + o];
        }
        #pragma unroll
        for (int off = 16; off; off >>= 1) acc += __shfl_xor_sync(0xffffffffu, acc, off);
        if (lane == 0) g_dHW[hd * 33 + j] = acc;
    }
}

// =================================================================================
// delta[hb][m] = wt . x_m + bq.pos_m + bq.bk    (warp per (hb,m))
// =================================================================================
__global__ void delta_kernel()
{
    int hb = blockIdx.y, hd = hb >> 5;
    int m = blockIdx.x * 8 + (threadIdx.x >> 5);
    int lane = threadIdx.x & 31;
    const bf16* xh = g_XTh + ((size_t)hb * NN + m) * CH;
    const bf16* xl = g_XTl + ((size_t)hb * NN + m) * CH;
    const float* wt = g_wt + hd * CH;
    float acc = 0.f;
    for (int c = lane; c < CH; c += 32)
        acc += (bf(xh[c]) + bf(xl[c])) * wt[c];
    #pragma unroll
    for (int off = 16; off; off >>= 1) acc += __shfl_xor_sync(0xffffffffu, acc, off);
    if (lane == 0)
        g_DELTA[hb * NN + m] = acc + g_dHW[hd * 33 + (m >> 4)]
                             + g_dHW[hd * 33 + 16 + (m & 15)] + g_dHW[hd * 33 + 32];
}

// =================================================================================
// K'' = Xt . M^T + Pq  (bf16 split), split-stored token-major [m][c]
// =================================================================================
__global__ __launch_bounds__(256, 2) void kpp_mma()
{
    extern __shared__ bf16 smh[];
    int hb = blockIdx.z, hd = hb >> 5;
    size_t xoff = (size_t)hb * NN * CH;
    size_t moff = (size_t)hd * CH * CH;
    int rbase = blockIdx.y * 128;   // m
    int cbase = blockIdx.x * 128;   // c
    int tid = threadIdx.x;

    float acc[4][4][4] = {};
    run_gemm_bf(acc, smh,
                g_XTh + xoff + (size_t)rbase * CH, g_XTl + xoff + (size_t)rbase * CH, CH,
                g_Mh + moff + (size_t)cbase * CH,  g_Ml + moff + (size_t)cbase * CH,  CH,
                16, tid);

    int wm = (tid >> 5) & 1, wn = tid >> 6, lr = (tid & 31) >> 2, lc = tid & 3;
    bf16* dsth = g_Kh + xoff;
    bf16* dstl = g_Kl + xoff;
    int hdC = hd * CH;
    #pragma unroll
    for (int mf = 0; mf < 4; mf++) {
        #pragma unroll
        for (int nf = 0; nf < 4; nf++) {
            int c = cbase + wn * 32 + nf * 8 + lc * 2;
            #pragma unroll
            for (int rh = 0; rh < 2; rh++) {
                int m = rbase + wm * 64 + mf * 16 + lr + rh * 8;
                int yy = m >> 4, xx = m & 15;
                float vx = acc[mf][nf][rh * 2 + 0]
                         + g_PH[(size_t)(hdC + c) * 16 + yy] + g_PW[(size_t)(hdC + c) * 16 + xx];
                float vy = acc[mf][nf][rh * 2 + 1]
                         + g_PH[(size_t)(hdC + c + 1) * 16 + yy] + g_PW[(size_t)(hdC + c + 1) * 16 + xx];
                bf16 hx = bhi(vx), hy = bhi(vy);
                size_t off = (size_t)m * CH + c;
                *(bf162*)(dsth + off) = bf162(hx, hy);
                *(bf162*)(dstl + off) = bf162(blo(vx, hx), blo(vy, hy));
            }
        }
    }
}

// =================================================================================
// V projection (bf16 split): D[o][m], tf32-rounded fp32 out
// =================================================================================
__global__ __launch_bounds__(256, 2) void v_mma(const float* __restrict__ vB)
{
    extern __shared__ bf16 smh[];
    int hb = blockIdx.z, hd = hb >> 5;
    size_t woff = (size_t)hd * CH * CH;
    size_t xoff = (size_t)hb * NN * CH;
    int rbase = blockIdx.y * 128;   // o
    int cbase = blockIdx.x * 128;   // m
    int tid = threadIdx.x;

    float acc[4][4][4] = {};
    run_gemm_bf(acc, smh,
                g_Wh + woff + (size_t)rbase * CH,  g_Wl + woff + (size_t)rbase * CH,  CH,
                g_XTh + xoff + (size_t)cbase * CH, g_XTl + xoff + (size_t)cbase * CH, CH,
                16, tid);

    int wm = (tid >> 5) & 1, wn = tid >> 6, lr = (tid & 31) >> 2, lc = tid & 3;
    const float* bias = vB + hd * CH;
    float* dst = g_V + (size_t)hb * CH * NN;
    #pragma unroll
    for (int mf = 0; mf < 4; mf++) {
        #pragma unroll
        for (int nf = 0; nf < 4; nf++) {
            int m = cbase + wn * 32 + nf * 8 + lc * 2;
            #pragma unroll
            for (int rh = 0; rh < 2; rh++) {
                int o = rbase + wm * 64 + mf * 16 + lr + rh * 8;
                float bv = bias[o];
                *(float2*)(dst + (size_t)o * NN + m) =
                    make_float2(tfround(acc[mf][nf][rh * 2 + 0] + bv),
                                tfround(acc[mf][nf][rh * 2 + 1] + bv));
            }
        }
    }
}

// =================================================================================
// energy (bf16 split): E[n][m] = Xt[n][:] . K''[m][:], fp32 out
// =================================================================================
__global__ __launch_bounds__(256, 2) void energy_mma()
{
    extern __shared__ bf16 smh[];
    int hb = blockIdx.z;
    size_t xoff = (size_t)hb * NN * CH;
    int rbase = blockIdx.y * 128, cbase = blockIdx.x * 128;
    int tid = threadIdx.x;

    float acc[4][4][4] = {};
    run_gemm_bf(acc, smh,
                g_XTh + xoff + (size_t)rbase * CH, g_XTl + xoff + (size_t)rbase * CH, CH,
                g_Kh + xoff + (size_t)cbase * CH,  g_Kl + xoff + (size_t)cbase * CH,  CH,
                16, tid);

    int wm = (tid >> 5) & 1, wn = tid >> 6, lr = (tid & 31) >> 2, lc = tid & 3;
    float* dst = g_E + (size_t)hb * NN * NN;
    #pragma unroll
    for (int mf = 0; mf < 4; mf++) {
        #pragma unroll
        for (int nf = 0; nf < 4; nf++) {
            int m = cbase + wn * 32 + nf * 8 + lc * 2;
            #pragma unroll
            for (int rh = 0; rh < 2; rh++) {
                int n = rbase + wm * 64 + mf * 16 + lr + rh * 8;
                *(float2*)(dst + (size_t)n * NN + m) =
                    make_float2(acc[mf][nf][rh * 2 + 0], acc[mf][nf][rh * 2 + 1]);
            }
        }
    }
}

// =================================================================================
// softmax over last dim (256) of (e + delta[m]); attn stored tf32-rounded
// =================================================================================
__global__ __launch_bounds__(256) void softmax_kernel()
{
    int warp = threadIdx.x >> 5, lane = threadIdx.x & 31;
    int row = blockIdx.x * 8 + warp;
    float* e = g_E + (size_t)row * NN;
    const float* dl = g_DELTA + (size_t)(row >> 8) * NN;

    float4 a = ((float4*)e)[lane];
    float4 b = ((float4*)e)[lane + 32];
    float4 d0 = ((const float4*)dl)[lane];
    float4 d1 = ((const float4*)dl)[lane + 32];
    a.x += d0.x; a.y += d0.y; a.z += d0.z; a.w += d0.w;
    b.x += d1.x; b.y += d1.y; b.z += d1.z; b.w += d1.w;

    float m = fmaxf(fmaxf(fmaxf(a.x, a.y), fmaxf(a.z, a.w)),
                    fmaxf(fmaxf(b.x, b.y), fmaxf(b.z, b.w)));
    #pragma unroll
    for (int off = 16; off; off >>= 1) m = fmaxf(m, __shfl_xor_sync(0xffffffffu, m, off));
    a.x = __expf(a.x - m); a.y = __expf(a.y - m); a.z = __expf(a.z - m); a.w = __expf(a.w - m);
    b.x = __expf(b.x - m); b.y = __expf(b.y - m); b.z = __expf(b.z - m); b.w = __expf(b.w - m);
    float s = a.x + a.y + a.z + a.w + b.x + b.y + b.z + b.w;
    #pragma unroll
    for (int off = 16; off; off >>= 1) s += __shfl_xor_sync(0xffffffffu, s, off);
    float inv = 1.0f / s;
    a.x = tfround(a.x * inv); a.y = tfround(a.y * inv);
    a.z = tfround(a.z * inv); a.w = tfround(a.w * inv);
    b.x = tfround(b.x * inv); b.y = tfround(b.y * inv);
    b.z = tfround(b.z * inv); b.w = tfround(b.w * inv);
    ((float4*)e)[lane] = a;
    ((float4*)e)[lane + 32] = b;
}

// =================================================================================
// AV (tf32, pre-rounded operands): Ot[n][c] = attn[n][:] . V[c][:]
// =================================================================================
__global__ __launch_bounds__(256, 2) void av_mma()
{
    extern __shared__ float sm[];
    int hb = blockIdx.z;
    const float* A = g_E + (size_t)hb * NN * NN;
    const float* V = g_V + (size_t)hb * CH * NN;
    int rbase = blockIdx.y * 128;   // n
    int cbase = blockIdx.x * 128;   // c
    int tid = threadIdx.x;

    float acc[4][4][4] = {};
    run_gemm_tf<false>(acc, sm, A + (size_t)rbase * NN, NN,
                       V + (size_t)cbase * NN, NN, 8, nullptr, 0, tid);

    int wm = (tid >> 5) & 1, wn = tid >> 6, lr = (tid & 31) >> 2, lc = tid & 3;
    float* dst = g_Ot + (size_t)hb * NN * CH;
    #pragma unroll
    for (int mf = 0; mf < 4; mf++) {
        #pragma unroll
        for (int nf = 0; nf < 4; nf++) {
            int c = cbase + wn * 32 + nf * 8 + lc * 2;
            #pragma unroll
            for (int rh = 0; rh < 2; rh++) {
                int n = rbase + wm * 64 + mf * 16 + lr + rh * 8;
                *(float2*)(dst + (size_t)n * CH + c) =
                    make_float2(acc[mf][nf][rh * 2 + 0], acc[mf][nf][rh * 2 + 1]);
            }
        }
    }
}

// =================================================================================
// msw gating: one warp per (b, n)
// =================================================================================
__global__ __launch_bounds__(256) void msw_kernel(
    const float* __restrict__ mswW, const float* __restrict__ gg,
    const float* __restrict__ bbt,  const float* __restrict__ mmn,
    const float* __restrict__ vvr)
{
    int b = blockIdx.y;
    int n = blockIdx.x * 8 + (threadIdx.x >> 5);
    int lane = threadIdx.x & 31;
    float a0 = 0.f, a1 = 0.f, a2 = 0.f, a3 = 0.f;
    #pragma unroll
    for (int hd = 0; hd < NHEADS; hd++) {
        const float* base = g_Ot + ((size_t)(hd * BATCH + b) * NN + n) * CH;
        const float* w = mswW + hd * CH;
        for (int c = lane; c < CH; c += 32) {
            float xv = base[c];
            a0 += xv * w[c];
            a1 += xv * w[2560 + c];
            a2 += xv * w[2 * 2560 + c];
            a3 += xv * w[3 * 2560 + c];
        }
    }
    #pragma unroll
    for (int off = 16; off; off >>= 1) {
        a0 += __shfl_xor_sync(0xffffffffu, a0, off);
        a1 += __shfl_xor_sync(0xffffffffu, a1, off);
        a2 += __shfl_xor_sync(0xffffffffu, a2, off);
        a3 += __shfl_xor_sync(0xffffffffu, a3, off);
    }
    if (lane < 4) {
        float acc = lane == 0 ? a0 : lane == 1 ? a1 : lane == 2 ? a2 : a3;
        float z = (acc - mmn[lane]) * (gg[lane] * rsqrtf(vvr[lane] + BN_EPS)) + bbt[lane];
        g_WGT[(b * 4 + lane) * NN + n] = 1.f / (1.f + __expf(-z));
    }
}

// =================================================================================
// combine: x_ms[b][n][c] = Ot4 + sum_i w_i[n] * Ot_i   (tf32-rounded store)
// =================================================================================
__global__ __launch_bounds__(256) void combine_kernel()
{
    int idx = blockIdx.x * 256 + threadIdx.x;
    int b = idx >> 17;
    int n = (idx >> 9) & 255;
    const float* w = g_WGT + b * 4 * NN;
    size_t hs = (size_t)BATCH * NN * CH;
    size_t off = (size_t)idx;
    float r = g_Ot[4 * hs + off]
            + w[n]          * g_Ot[off]
            + w[NN + n]     * g_Ot[hs + off]
            + w[2 * NN + n] * g_Ot[2 * hs + off]
            + w[3 * NN + n] * g_Ot[3 * hs + off];
    g_MS[off] = tfround(r);
}

// =================================================================================
// conv3x3 implicit GEMM (tf32, pre-rounded operands): D[o][n], K = 4608
// =================================================================================
__global__ __launch_bounds__(256, 2) void conv_mma()
{
    extern __shared__ float sm[];
    int b = blockIdx.z;
    int rbase = blockIdx.y * 128;   // o
    int cbase = blockIdx.x * 128;   // n
    const float* MSb = g_MS + (size_t)b * NN * CH;
    int tid = threadIdx.x;

    float acc[4][4][4] = {};
    run_gemm_tf<true>(acc, sm, g_Wp + (size_t)rbase * KCONV, KCONV,
                      nullptr, 0, 144, MSb, cbase, tid);

    int wm = (tid >> 5) & 1, wn = tid >> 6, lr = (tid & 31) >> 2, lc = tid & 3;
    float* dst = g_CV + (size_t)b * CH * NN;
    #pragma unroll
    for (int mf = 0; mf < 4; mf++) {
        #pragma unroll
        for (int nf = 0; nf < 4; nf++) {
            int n = cbase + wn * 32 + nf * 8 + lc * 2;
            #pragma unroll
            for (int rh = 0; rh < 2; rh++) {
                int o = rbase + wm * 64 + mf * 16 + lr + rh * 8;
                *(float2*)(dst + (size_t)o * NN + n) =
                    make_float2(acc[mf][nf][rh * 2 + 0], acc[mf][nf][rh * 2 + 1]);
            }
        }
    }
}

// =================================================================================
// final: out = relu(bn_top(relu(bn_fus(conv)) + x))
// =================================================================================
__global__ __launch_bounds__(256) void final_kernel(
    const float* __restrict__ x,
    const float* __restrict__ fg, const float* __restrict__ fb,
    const float* __restrict__ fm, const float* __restrict__ fv,
    const float* __restrict__ tg, const float* __restrict__ tb,
    const float* __restrict__ tm, const float* __restrict__ tv,
    float* __restrict__ out)
{
    int idx = blockIdx.x * 256 + threadIdx.x;
    int c = (idx >> 8) & 511;
    float t = g_CV[idx];
    t = (t - fm[c]) * (fg[c] * rsqrtf(fv[c] + BN_EPS)) + fb[c];
    t = fmaxf(t, 0.f);
    t += x[idx];
    t = (t - tm[c]) * (tg[c] * rsqrtf(tv[c] + BN_EPS)) + tb[c];
    out[idx] = fmaxf(t, 0.f);
}

// =================================================================================
extern "C" void kernel_launch(void* const* d_in, const int* in_sizes, int n_in,
                              void* d_out, int out_size)
{
    const float* x0   = (const float*)d_in[0];
    const float* x1   = (const float*)d_in[1];
    const float* x2   = (const float*)d_in[2];
    const float* x3   = (const float*)d_in[3];
    const float* x4   = (const float*)d_in[4];
    const float* qW   = (const float*)d_in[5];
    const float* qB   = (const float*)d_in[6];
    const float* kW   = (const float*)d_in[7];
    const float* kB   = (const float*)d_in[8];
    const float* vW   = (const float*)d_in[9];
    const float* vB   = (const float*)d_in[10];
    const float* relH = (const float*)d_in[11];
    const float* relW = (const float*)d_in[12];
    const float* mswW = (const float*)d_in[13];
    const float* mswg = (const float*)d_in[14];
    const float* mswb = (const float*)d_in[15];
    const float* mswm = (const float*)d_in[16];
    const float* mswv = (const float*)d_in[17];
    const float* fusW = (const float*)d_in[18];
    const float* fusg = (const float*)d_in[19];
    const float* fusb = (const float*)d_in[20];
    const float* fusm = (const float*)d_in[21];
    const float* fusv = (const float*)d_in[22];
    const float* topg = (const float*)d_in[23];
    const float* topb = (const float*)d_in[24];
    const float* topm = (const float*)d_in[25];
    const float* topv = (const float*)d_in[26];
    float* out = (float*)d_out;

    cudaFuncSetAttribute(m_mma,      cudaFuncAttributeMaxDynamicSharedMemorySize, SMEMB_BYTES);
    cudaFuncSetAttribute(kpp_mma,    cudaFuncAttributeMaxDynamicSharedMemorySize, SMEMB_BYTES);
    cudaFuncSetAttribute(v_mma,      cudaFuncAttributeMaxDynamicSharedMemorySize, SMEMB_BYTES);
    cudaFuncSetAttribute(energy_mma, cudaFuncAttributeMaxDynamicSharedMemorySize, SMEMB_BYTES);
    cudaFuncSetAttribute(av_mma,     cudaFuncAttributeMaxDynamicSharedMemorySize, SMEM_BYTES);
    cudaFuncSetAttribute(conv_mma,   cudaFuncAttributeMaxDynamicSharedMemorySize, SMEM_BYTES);

    transpose_kernel<<<dim3(8, 16, NHEADS * BATCH), dim3(32, 8)>>>(x0, x1, x2, x3, x4);
    wtrans_kernel<<<dim3(16, 16, 2 * NHEADS), dim3(32, 8)>>>(qW, kW);
    wsplit_kernel<<<NHEADS * CH * CH / 256, 256>>>(vW);
    permW_kernel<<<CH, 256>>>(fusW);

    // prep: M = Wq^T Wk, PH/PW, wt, dHW, delta
    m_mma<<<dim3(4, 4, NHEADS), 256, SMEMB_BYTES>>>();
    php_kernel<<<dim3(CH / 64, NHEADS), 256>>>(relH, relW);
    wt_kernel<<<dim3(CH / 8, NHEADS), 256>>>(qB);
    dhw_kernel<<<NHEADS, 256>>>(relH, relW, qB, kB);
    delta_kernel<<<dim3(NN / 8, NHEADS * BATCH), 256>>>();

    // K'' = Xt M^T + Pq
    kpp_mma<<<dim3(4, 2, NHEADS * BATCH), 256, SMEMB_BYTES>>>();

    // V projection
    v_mma<<<dim3(2, 4, NHEADS * BATCH), 256, SMEMB_BYTES>>>(vB);

    // energy = Xt . K''
    energy_mma<<<dim3(2, 2, NHEADS * BATCH), 256, SMEMB_BYTES>>>();

    softmax_kernel<<<(NHEADS * BATCH * NN) / 8, 256>>>();

    av_mma<<<dim3(4, 2, NHEADS * BATCH), 256, SMEM_BYTES>>>();

    msw_kernel<<<dim3(NN / 8, BATCH), 256>>>(mswW, mswg, mswb, mswm, mswv);
    combine_kernel<<<(BATCH * NN * CH) / 256, 256>>>();

    conv_mma<<<dim3(2, 4, BATCH), 256, SMEM_BYTES>>>();

    final_kernel<<<(BATCH * CH * NN) / 256, 256>>>(
        x4, fusg, fusb, fusm, fusv, topg, topb, topm, topv, out);
}

// round 17
// speedup vs baseline: 1.1488x; 1.0097x over previous
#include <cuda_runtime.h>
#include <cuda_bf16.h>
#include <cstdint>

#define NHEADS 5
#define BATCH  32
#define CH     512
#define NN     256
#define KCONV  4608
#define BN_EPS 1e-5f

typedef __nv_bfloat16 bf16;
typedef __nv_bfloat162 bf162;

// ---------------- scratch (device globals) ----------------
__device__ bf16 g_XTh[(size_t)NHEADS * BATCH * NN * CH];   // x transposed hi [hb][n][c]
__device__ bf16 g_XTl[(size_t)NHEADS * BATCH * NN * CH];   // lo
__device__ bf16 g_Wh[(size_t)NHEADS * CH * CH];            // V weights hi [hd][o][c]
__device__ bf16 g_Wl[(size_t)NHEADS * CH * CH];
__device__ bf16 g_WqTh[(size_t)NHEADS * CH * CH];          // Wq^T hi [hd][c][o]
__device__ bf16 g_WqTl[(size_t)NHEADS * CH * CH];
__device__ bf16 g_WkTh[(size_t)NHEADS * CH * CH];          // Wk^T hi [hd][c][o]
__device__ bf16 g_WkTl[(size_t)NHEADS * CH * CH];
__device__ bf16 g_Mh[(size_t)NHEADS * CH * CH];            // M = Wq^T Wk  [hd][c][c']
__device__ bf16 g_Ml[(size_t)NHEADS * CH * CH];
__device__ bf16 g_Kh[(size_t)NHEADS * BATCH * NN * CH];    // K'' token-major hi
__device__ bf16 g_Kl[(size_t)NHEADS * BATCH * NN * CH];
__device__ float g_PH[(size_t)NHEADS * CH * 16];           // Wq^T relH
__device__ float g_PW[(size_t)NHEADS * CH * 16];           // Wq^T relW
__device__ float g_wt[NHEADS * CH];                        // Wk^T bq
__device__ float g_dHW[NHEADS * 33];                       // bq.relH[16], bq.relW[16], bq.bk
__device__ float g_DELTA[NHEADS * BATCH * NN];             // column bias
__device__ float g_V [(size_t)NHEADS * BATCH * CH * NN];   // V channel-major, tf32-rounded
__device__ float g_E [(size_t)NHEADS * BATCH * NN * NN];   // energy -> attn (tf32-rounded)
__device__ float g_Ot[(size_t)NHEADS * BATCH * NN * CH];   // attn out token-major fp32
__device__ float g_MS[(size_t)BATCH * NN * CH];            // x_ms token-major, tf32-rounded
__device__ float g_CV[(size_t)BATCH * CH * NN];            // conv out channel-major
__device__ float g_Wp[(size_t)CH * KCONV];                 // permuted conv weights, tf32-rounded

// ---------------- low-level helpers ----------------
__device__ __forceinline__ uint32_t smem_u32(const void* p) {
    uint32_t a;
    asm("{ .reg .u64 t; cvta.to.shared.u64 t, %1; cvt.u32.u64 %0, t; }" : "=r"(a) : "l"(p));
    return a;
}
__device__ __forceinline__ void cpa16(uint32_t s, const void* g, int bytes) {
    asm volatile("cp.async.cg.shared.global [%0], [%1], 16, %2;" :: "r"(s), "l"(g), "r"(bytes));
}
__device__ __forceinline__ void cp_commit() { asm volatile("cp.async.commit_group;"); }
template<int N> __device__ __forceinline__ void cp_wait() {
    asm volatile("cp.async.wait_group %0;" :: "n"(N));
}
__device__ __forceinline__ uint32_t f2tf(float x) {
    uint32_t r; asm("cvt.rna.tf32.f32 %0, %1;" : "=r"(r) : "f"(x)); return r;
}
__device__ __forceinline__ float tfround(float x) { return __uint_as_float(f2tf(x)); }
__device__ __forceinline__ void mma8(float* c, const uint32_t* a, const uint32_t* b) {
    asm volatile("mma.sync.aligned.m16n8k8.row.col.f32.tf32.tf32.f32 "
        "{%0,%1,%2,%3}, {%4,%5,%6,%7}, {%8,%9}, {%0,%1,%2,%3};"
        : "+f"(c[0]), "+f"(c[1]), "+f"(c[2]), "+f"(c[3])
        : "r"(a[0]), "r"(a[1]), "r"(a[2]), "r"(a[3]), "r"(b[0]), "r"(b[1]));
}
__device__ __forceinline__ void mma16(float* c, const uint32_t* a, const uint32_t* b) {
    asm volatile("mma.sync.aligned.m16n8k16.row.col.f32.bf16.bf16.f32 "
        "{%0,%1,%2,%3}, {%4,%5,%6,%7}, {%8,%9}, {%0,%1,%2,%3};"
        : "+f"(c[0]), "+f"(c[1]), "+f"(c[2]), "+f"(c[3])
        : "r"(a[0]), "r"(a[1]), "r"(a[2]), "r"(a[3]), "r"(b[0]), "r"(b[1]));
}
__device__ __forceinline__ bf16 bhi(float v) { return __float2bfloat16_rn(v); }
__device__ __forceinline__ bf16 blo(float v, bf16 h) {
    return __float2bfloat16_rn(v - __bfloat162float(h));
}
__device__ __forceinline__ float bf(bf16 v) { return __bfloat162float(v); }

// ================= bf16-split GEMM machinery =================
#define HSTR 40
#define HTILE (128 * HSTR)
#define HSTAGE (4 * HTILE)
#define SMEMB_BYTES (2 * HSTAGE * 2)    // 81920 B

__device__ __forceinline__ void ld_tile_h(bf16* smT, const bf16* g, int ld, int tid) {
    #pragma unroll
    for (int i = 0; i < 2; i++) {
        int idx = tid + i * 256;
        int r = idx >> 2, q = idx & 3;
        cpa16(smem_u32(smT + r * HSTR + q * 8), g + (size_t)r * ld + q * 8, 16);
    }
}

__device__ __forceinline__ void compute_chunk_bf(float cacc[4][4][4],
    const bf16* S, int wm, int wn, int lr, int lc)
{
    const bf16* Ah = S;
    const bf16* Al = S + HTILE;
    const bf16* Bh = S + 2 * HTILE;
    const bf16* Bl = S + 3 * HTILE;
    #pragma unroll
    for (int ks = 0; ks < 2; ks++) {
        int kk = ks * 16 + 2 * lc;
        uint32_t bh[4][2], bl[4][2];
        #pragma unroll
        for (int nf = 0; nf < 4; nf++) {
            int rb = (wn * 32 + nf * 8 + lr) * HSTR + kk;
            bh[nf][0] = *(const uint32_t*)(Bh + rb);
            bh[nf][1] = *(const uint32_t*)(Bh + rb + 8);
            bl[nf][0] = *(const uint32_t*)(Bl + rb);
            bl[nf][1] = *(const uint32_t*)(Bl + rb + 8);
        }
        #pragma unroll
        for (int mf = 0; mf < 4; mf++) {
            int ra = (wm * 64 + mf * 16 + lr) * HSTR + kk;
            uint32_t ah[4], al[4];
            ah[0] = *(const uint32_t*)(Ah + ra);
            ah[1] = *(const uint32_t*)(Ah + ra + 8 * HSTR);
            ah[2] = *(const uint32_t*)(Ah + ra + 8);
            ah[3] = *(const uint32_t*)(Ah + ra + 8 * HSTR + 8);
            al[0] = *(const uint32_t*)(Al + ra);
            al[1] = *(const uint32_t*)(Al + ra + 8 * HSTR);
            al[2] = *(const uint32_t*)(Al + ra + 8);
            al[3] = *(const uint32_t*)(Al + ra + 8 * HSTR + 8);
            #pragma unroll
            for (int nf = 0; nf < 4; nf++) {
                mma16(cacc[mf][nf], ah, bh[nf]);
                mma16(cacc[mf][nf], ah, bl[nf]);
                mma16(cacc[mf][nf], al, bh[nf]);
            }
        }
    }
}

__device__ __forceinline__ void run_gemm_bf(float cacc[4][4][4], bf16* sm,
    const bf16* Ah, const bf16* Al, int lda,
    const bf16* Bh, const bf16* Bl, int ldb, int nchunks, int tid)
{
    ld_tile_h(sm,             Ah, lda, tid);
    ld_tile_h(sm + HTILE,     Al, lda, tid);
    ld_tile_h(sm + 2 * HTILE, Bh, ldb, tid);
    ld_tile_h(sm + 3 * HTILE, Bl, ldb, tid);
    cp_commit();

    int wm = (tid >> 5) & 1, wn = tid >> 6, lr = (tid & 31) >> 2, lc = tid & 3;

    for (int c = 0; c < nchunks; c++) {
        if (c + 1 < nchunks) {
            bf16* d = sm + ((c + 1) & 1) * HSTAGE;
            int ko = (c + 1) * 32;
            ld_tile_h(d,             Ah + ko, lda, tid);
            ld_tile_h(d + HTILE,     Al + ko, lda, tid);
            ld_tile_h(d + 2 * HTILE, Bh + ko, ldb, tid);
            ld_tile_h(d + 3 * HTILE, Bl + ko, ldb, tid);
            cp_commit();
            cp_wait<1>();
        } else {
            cp_wait<0>();
        }
        __syncthreads();
        compute_chunk_bf(cacc, sm + (c & 1) * HSTAGE, wm, wn, lr, lc);
        __syncthreads();
    }
}

// ================= tf32 GEMM machinery (AV + conv); operands pre-rounded =================
#define ASZ (128 * 36)
#define STG (2 * ASZ)
#define SMEM_BYTES (2 * STG * 4)

__device__ __forceinline__ void ld_tile(float* smT, const float* g, int ld, int tid) {
    #pragma unroll
    for (int i = 0; i < 4; i++) {
        int idx = tid + i * 256;
        int r = idx >> 3, q = idx & 7;
        cpa16(smem_u32(smT + r * 36 + q * 4), g + (size_t)r * ld + q * 4, 16);
    }
}
__device__ __forceinline__ void ld_conv(float* smT, const float* MSb, int n0, int ch, int tid) {
    int s = ch >> 4;
    int cib = (ch & 15) * 32;
    int kh = s / 3, kw = s - kh * 3;
    #pragma unroll
    for (int i = 0; i < 4; i++) {
        int idx = tid + i * 256;
        int r = idx >> 3, q = idx & 7;
        int n = n0 + r;
        int y = (n >> 4) + kh - 1, x = (n & 15) + kw - 1;
        bool ok = ((unsigned)y < 16u) && ((unsigned)x < 16u);
        const float* src = MSb + (ok ? ((y << 4) + x) * CH : 0) + cib + q * 4;
        cpa16(smem_u32(smT + r * 36 + q * 4), src, ok ? 16 : 0);
    }
}

// operands in smem are already tf32-rounded fp32 — pass raw bits, no cvt.
__device__ __forceinline__ void compute_chunk_tf(float cacc[4][4][4],
    const float* As, const float* Bs, int wm, int wn, int lr, int lc)
{
    #pragma unroll
    for (int ks = 0; ks < 4; ks++) {
        int kk = ks * 8;
        uint32_t bhv[4][2];
        #pragma unroll
        for (int nf = 0; nf < 4; nf++) {
            #pragma unroll
            for (int j = 0; j < 2; j++)
                bhv[nf][j] = __float_as_uint(Bs[(wn * 32 + nf * 8 + lr) * 36 + kk + lc + j * 4]);
        }
        #pragma unroll
        for (int mf = 0; mf < 4; mf++) {
            uint32_t ahv[4];
            #pragma unroll
            for (int r = 0; r < 4; r++)
                ahv[r] = __float_as_uint(As[(wm * 64 + mf * 16 + lr + (r & 1) * 8) * 36 + kk + lc + (r >> 1) * 4]);
            #pragma unroll
            for (int nf = 0; nf < 4; nf++)
                mma8(cacc[mf][nf], ahv, bhv[nf]);
        }
    }
}

template<bool CONV>
__device__ __forceinline__ void run_gemm_tf(float cacc[4][4][4], float* sm,
    const float* Aeff, int lda, const float* Beff, int ldb,
    int nchunks, const float* MSb, int n0, int tid)
{
    ld_tile(sm, Aeff, lda, tid);
    if (CONV) ld_conv(sm + ASZ, MSb, n0, 0, tid);
    else      ld_tile(sm + ASZ, Beff, ldb, tid);
    cp_commit();

    int wm = (tid >> 5) & 1, wn = tid >> 6, lr = (tid & 31) >> 2, lc = tid & 3;

    for (int c = 0; c < nchunks; c++) {
        if (c + 1 < nchunks) {
            float* d = sm + ((c + 1) & 1) * STG;
            ld_tile(d, Aeff + (c + 1) * 32, lda, tid);
            if (CONV) ld_conv(d + ASZ, MSb, n0, c + 1, tid);
            else      ld_tile(d + ASZ, Beff + (c + 1) * 32, ldb, tid);
            cp_commit();
            cp_wait<1>();
        } else {
            cp_wait<0>();
        }
        __syncthreads();
        const float* As = sm + (c & 1) * STG;
        compute_chunk_tf(cacc, As, As + ASZ, wm, wn, lr, lc);
        __syncthreads();
    }
}

// =================================================================================
// transpose x [c][n] -> XT hi/lo [hb][n][c]
// =================================================================================
__global__ void transpose_kernel(
    const float* __restrict__ x0, const float* __restrict__ x1,
    const float* __restrict__ x2, const float* __restrict__ x3,
    const float* __restrict__ x4)
{
    __shared__ float t[32][33];
    int hb = blockIdx.z, hd = hb >> 5, b = hb & 31;
    const float* X = (hd == 0 ? x0 : hd == 1 ? x1 : hd == 2 ? x2 : hd == 3 ? x3 : x4)
                     + (size_t)b * CH * NN;
    int c0 = blockIdx.y * 32, n0 = blockIdx.x * 32;
    int tx = threadIdx.x, ty = threadIdx.y;
    #pragma unroll
    for (int i = 0; i < 32; i += 8)
        t[ty + i][tx] = X[(size_t)(c0 + ty + i) * NN + n0 + tx];
    __syncthreads();
    size_t base = (size_t)hb * NN * CH;
    #pragma unroll
    for (int i = 0; i < 32; i += 8) {
        float v = t[tx][ty + i];
        bf16 h = bhi(v);
        size_t off = base + (size_t)(n0 + ty + i) * CH + c0 + tx;
        g_XTh[off] = h;
        g_XTl[off] = blo(v, h);
    }
}

// =================================================================================
// transpose-split Wq, Wk -> WqT/WkT hi/lo  [hd][c][o]
// =================================================================================
__global__ void wtrans_kernel(const float* __restrict__ qW, const float* __restrict__ kW)
{
    __shared__ float t[32][33];
    int z = blockIdx.z;
    int isK = z >= NHEADS;
    int hd = isK ? z - NHEADS : z;
    const float* W = (isK ? kW : qW) + (size_t)hd * CH * CH;
    bf16* dh = (isK ? g_WkTh : g_WqTh) + (size_t)hd * CH * CH;
    bf16* dl = (isK ? g_WkTl : g_WqTl) + (size_t)hd * CH * CH;
    int o0 = blockIdx.y * 32, c0 = blockIdx.x * 32;
    int tx = threadIdx.x, ty = threadIdx.y;
    #pragma unroll
    for (int i = 0; i < 32; i += 8)
        t[ty + i][tx] = W[(size_t)(o0 + ty + i) * CH + c0 + tx];
    __syncthreads();
    #pragma unroll
    for (int i = 0; i < 32; i += 8) {
        float v = t[tx][ty + i];
        bf16 h = bhi(v);
        size_t off = (size_t)(c0 + ty + i) * CH + o0 + tx;
        dh[off] = h;
        dl[off] = blo(v, h);
    }
}

// =================================================================================
// split V weights -> bf16 hi/lo
// =================================================================================
__global__ void wsplit_kernel(const float* __restrict__ vW)
{
    size_t i = (size_t)blockIdx.x * 256 + threadIdx.x;
    float v = vW[i];
    bf16 h = bhi(v);
    g_Wh[i] = h;
    g_Wl[i] = blo(v, h);
}

// =================================================================================
// permute conv weights (tf32-rounded at store)
// =================================================================================
__global__ void permW_kernel(const float* __restrict__ fusW)
{
    int o = blockIdx.x;
    for (int k = threadIdx.x; k < KCONV; k += 256) {
        int s = k >> 9, ci = k & 511;
        g_Wp[(size_t)o * KCONV + k] = tfround(fusW[(size_t)o * KCONV + ci * 9 + s]);
    }
}

// =================================================================================
// M = Wq^T Wk  per head (bf16 split GEMM), output split to Mh/Ml [c][c']
// =================================================================================
__global__ __launch_bounds__(256, 2) void m_mma()
{
    extern __shared__ bf16 smh[];
    int hd = blockIdx.z;
    size_t w = (size_t)hd * CH * CH;
    int rbase = blockIdx.y * 128;   // c
    int cbase = blockIdx.x * 128;   // c'
    int tid = threadIdx.x;

    float acc[4][4][4] = {};
    run_gemm_bf(acc, smh,
                g_WqTh + w + (size_t)rbase * CH, g_WqTl + w + (size_t)rbase * CH, CH,
                g_WkTh + w + (size_t)cbase * CH, g_WkTl + w + (size_t)cbase * CH, CH,
                16, tid);

    int wm = (tid >> 5) & 1, wn = tid >> 6, lr = (tid & 31) >> 2, lc = tid & 3;
    #pragma unroll
    for (int mf = 0; mf < 4; mf++) {
        #pragma unroll
        for (int nf = 0; nf < 4; nf++) {
            int cp = cbase + wn * 32 + nf * 8 + lc * 2;
            #pragma unroll
            for (int rh = 0; rh < 2; rh++) {
                int c = rbase + wm * 64 + mf * 16 + lr + rh * 8;
                float vx = acc[mf][nf][rh * 2 + 0];
                float vy = acc[mf][nf][rh * 2 + 1];
                bf16 hx = bhi(vx), hy = bhi(vy);
                size_t off = w + (size_t)c * CH + cp;
                *(bf162*)(g_Mh + off) = bf162(hx, hy);
                *(bf162*)(g_Ml + off) = bf162(blo(vx, hx), blo(vy, hy));
            }
        }
    }
}

// =================================================================================
// PH = Wq^T relH, PW = Wq^T relW  — tiled through smem.
// =================================================================================
__global__ __launch_bounds__(256) void php_kernel(
    const float* __restrict__ relH, const float* __restrict__ relW)
{
    __shared__ float sW[64][65];
    __shared__ float sR[64][33];
    int hd = blockIdx.y;
    int c0 = blockIdx.x * 64;
    int tid = threadIdx.x;
    int c = tid & 63, g = tid >> 6;
    const bf16* qh = g_WqTh + (size_t)hd * CH * CH;
    const bf16* ql = g_WqTl + (size_t)hd * CH * CH;

    float acc[8] = {};
    for (int ot = 0; ot < 8; ot++) {
        {
            int cc = tid >> 2, oo = (tid & 3) * 16;
            size_t base = (size_t)(c0 + cc) * CH + ot * 64 + oo;
            #pragma unroll
            for (int j = 0; j < 16; j++)
                sW[cc][oo + j] = bf(qh[base + j]) + bf(ql[base + j]);
        }
        {
            int oo = tid >> 2, j0 = (tid & 3) * 8;
            int og = ot * 64 + oo;
            #pragma unroll
            for (int j = 0; j < 8; j++) {
                int jj = j0 + j;
                sR[oo][jj] = (jj < 16)
                    ? relH[(size_t)(hd * CH + og) * 16 + jj]
                    : relW[(size_t)(hd * CH + og) * 16 + (jj - 16)];
            }
        }
        __syncthreads();
        #pragma unroll 8
        for (int o = 0; o < 64; o++) {
            float wv = sW[c][o];
            #pragma unroll
            for (int j = 0; j < 8; j++)
                acc[j] += wv * sR[o][g * 8 + j];
        }
        __syncthreads();
    }
    size_t idx = (size_t)(hd * CH + c0 + c) * 16;
    #pragma unroll
    for (int j = 0; j < 8; j++) {
        int jj = g * 8 + j;
        if (jj < 16) g_PH[idx + jj] = acc[j];
        else         g_PW[idx + (jj - 16)] = acc[j];
    }
}

// =================================================================================
// wt[hd][c] = Wk^T[c][:] . bq  (one warp per c)
// =================================================================================
__global__ void wt_kernel(const float* __restrict__ qB)
{
    int hd = blockIdx.y;
    int c = blockIdx.x * 8 + (threadIdx.x >> 5);
    int lane = threadIdx.x & 31;
    const bf16* kh = g_WkTh + ((size_t)hd * CH + c) * CH;
    const bf16* kl = g_WkTl + ((size_t)hd * CH + c) * CH;
    const float* bq = qB + hd * CH;
    float wt = 0.f;
    for (int o = lane; o < CH; o += 32)
        wt += (bf(kh[o]) + bf(kl[o])) * bq[o];
    #pragma unroll
    for (int off = 16; off; off >>= 1) wt += __shfl_xor_sync(0xffffffffu, wt, off);
    if (lane == 0) g_wt[hd * CH + c] = wt;
}

// =================================================================================
// dHW: bq.relH (16), bq.relW (16), bq.bk (1) per head
// =================================================================================
__global__ void dhw_kernel(const float* __restrict__ relH, const float* __restrict__ relW,
                           const float* __restrict__ qB, const float* __restrict__ kB)
{
    int hd = blockIdx.x;
    int warp = threadIdx.x >> 5, lane = threadIdx.x & 31;
    for (int j = warp; j < 33; j += 8) {
        float acc = 0.f;
        for (int o = lane; o < CH; o += 32) {
            float b = qB[hd * CH + o];
            if (j < 16)      acc += b * relH[(size_t)(hd * CH + o) * 16 + j];
            else if (j < 32) acc += b * relW[(size_t)(hd * CH + o) * 16 + (j - 16)];
            else             acc += b * kB[hd * CH + o];
        }
        #pragma unroll
        for (int off = 16; off; off >>= 1) acc += __shfl_xor_sync(0xffffffffu, acc, off);
        if (lane == 0) g_dHW[hd * 33 + j] = acc;
    }
}

// =================================================================================
// delta[hb][m] = wt . x_m + bq.pos_m + bq.bk    (warp per (hb,m))
// =================================================================================
__global__ void delta_kernel()
{
    int hb = blockIdx.y, hd = hb >> 5;
    int m = blockIdx.x * 8 + (threadIdx.x >> 5);
    int lane = threadIdx.x & 31;
    const bf16* xh = g_XTh + ((size_t)hb * NN + m) * CH;
    const bf16* xl = g_XTl + ((size_t)hb * NN + m) * CH;
    const float* wt = g_wt + hd * CH;
    float acc = 0.f;
    for (int c = lane; c < CH; c += 32)
        acc += (bf(xh[c]) + bf(xl[c])) * wt[c];
    #pragma unroll
    for (int off = 16; off; off >>= 1) acc += __shfl_xor_sync(0xffffffffu, acc, off);
    if (lane == 0)
        g_DELTA[hb * NN + m] = acc + g_dHW[hd * 33 + (m >> 4)]
                             + g_dHW[hd * 33 + 16 + (m & 15)] + g_dHW[hd * 33 + 32];
}

// =================================================================================
// K'' = Xt . M^T + Pq  (bf16 split), split-stored token-major [m][c]
// =================================================================================
__global__ __launch_bounds__(256, 2) void kpp_mma()
{
    extern __shared__ bf16 smh[];
    int hb = blockIdx.z, hd = hb >> 5;
    size_t xoff = (size_t)hb * NN * CH;
    size_t moff = (size_t)hd * CH * CH;
    int rbase = blockIdx.y * 128;   // m
    int cbase = blockIdx.x * 128;   // c
    int tid = threadIdx.x;

    float acc[4][4][4] = {};
    run_gemm_bf(acc, smh,
                g_XTh + xoff + (size_t)rbase * CH, g_XTl + xoff + (size_t)rbase * CH, CH,
                g_Mh + moff + (size_t)cbase * CH,  g_Ml + moff + (size_t)cbase * CH,  CH,
                16, tid);

    int wm = (tid >> 5) & 1, wn = tid >> 6, lr = (tid & 31) >> 2, lc = tid & 3;
    bf16* dsth = g_Kh + xoff;
    bf16* dstl = g_Kl + xoff;
    int hdC = hd * CH;
    #pragma unroll
    for (int mf = 0; mf < 4; mf++) {
        #pragma unroll
        for (int nf = 0; nf < 4; nf++) {
            int c = cbase + wn * 32 + nf * 8 + lc * 2;
            #pragma unroll
            for (int rh = 0; rh < 2; rh++) {
                int m = rbase + wm * 64 + mf * 16 + lr + rh * 8;
                int yy = m >> 4, xx = m & 15;
                float vx = acc[mf][nf][rh * 2 + 0]
                         + g_PH[(size_t)(hdC + c) * 16 + yy] + g_PW[(size_t)(hdC + c) * 16 + xx];
                float vy = acc[mf][nf][rh * 2 + 1]
                         + g_PH[(size_t)(hdC + c + 1) * 16 + yy] + g_PW[(size_t)(hdC + c + 1) * 16 + xx];
                bf16 hx = bhi(vx), hy = bhi(vy);
                size_t off = (size_t)m * CH + c;
                *(bf162*)(dsth + off) = bf162(hx, hy);
                *(bf162*)(dstl + off) = bf162(blo(vx, hx), blo(vy, hy));
            }
        }
    }
}

// =================================================================================
// V projection (bf16 split): D[o][m], tf32-rounded fp32 out
// =================================================================================
__global__ __launch_bounds__(256, 2) void v_mma(const float* __restrict__ vB)
{
    extern __shared__ bf16 smh[];
    int hb = blockIdx.z, hd = hb >> 5;
    size_t woff = (size_t)hd * CH * CH;
    size_t xoff = (size_t)hb * NN * CH;
    int rbase = blockIdx.y * 128;   // o
    int cbase = blockIdx.x * 128;   // m
    int tid = threadIdx.x;

    float acc[4][4][4] = {};
    run_gemm_bf(acc, smh,
                g_Wh + woff + (size_t)rbase * CH,  g_Wl + woff + (size_t)rbase * CH,  CH,
                g_XTh + xoff + (size_t)cbase * CH, g_XTl + xoff + (size_t)cbase * CH, CH,
                16, tid);

    int wm = (tid >> 5) & 1, wn = tid >> 6, lr = (tid & 31) >> 2, lc = tid & 3;
    const float* bias = vB + hd * CH;
    float* dst = g_V + (size_t)hb * CH * NN;
    #pragma unroll
    for (int mf = 0; mf < 4; mf++) {
        #pragma unroll
        for (int nf = 0; nf < 4; nf++) {
            int m = cbase + wn * 32 + nf * 8 + lc * 2;
            #pragma unroll
            for (int rh = 0; rh < 2; rh++) {
                int o = rbase + wm * 64 + mf * 16 + lr + rh * 8;
                float bv = bias[o];
                *(float2*)(dst + (size_t)o * NN + m) =
                    make_float2(tfround(acc[mf][nf][rh * 2 + 0] + bv),
                                tfround(acc[mf][nf][rh * 2 + 1] + bv));
            }
        }
    }
}

// =================================================================================
// energy (bf16 split): E[n][m] = Xt[n][:] . K''[m][:], fp32 out
// =================================================================================
__global__ __launch_bounds__(256, 2) void energy_mma()
{
    extern __shared__ bf16 smh[];
    int hb = blockIdx.z;
    size_t xoff = (size_t)hb * NN * CH;
    int rbase = blockIdx.y * 128, cbase = blockIdx.x * 128;
    int tid = threadIdx.x;

    float acc[4][4][4] = {};
    run_gemm_bf(acc, smh,
                g_XTh + xoff + (size_t)rbase * CH, g_XTl + xoff + (size_t)rbase * CH, CH,
                g_Kh + xoff + (size_t)cbase * CH,  g_Kl + xoff + (size_t)cbase * CH,  CH,
                16, tid);

    int wm = (tid >> 5) & 1, wn = tid >> 6, lr = (tid & 31) >> 2, lc = tid & 3;
    float* dst = g_E + (size_t)hb * NN * NN;
    #pragma unroll
    for (int mf = 0; mf < 4; mf++) {
        #pragma unroll
        for (int nf = 0; nf < 4; nf++) {
            int m = cbase + wn * 32 + nf * 8 + lc * 2;
            #pragma unroll
            for (int rh = 0; rh < 2; rh++) {
                int n = rbase + wm * 64 + mf * 16 + lr + rh * 8;
                *(float2*)(dst + (size_t)n * NN + m) =
                    make_float2(acc[mf][nf][rh * 2 + 0], acc[mf][nf][rh * 2 + 1]);
            }
        }
    }
}

// =================================================================================
// softmax over last dim (256) of (e + delta[m]); attn stored tf32-rounded
// =================================================================================
__global__ __launch_bounds__(256) void softmax_kernel()
{
    int warp = threadIdx.x >> 5, lane = threadIdx.x & 31;
    int row = blockIdx.x * 8 + warp;
    float* e = g_E + (size_t)row * NN;
    const float* dl = g_DELTA + (size_t)(row >> 8) * NN;

    float4 a = ((float4*)e)[lane];
    float4 b = ((float4*)e)[lane + 32];
    float4 d0 = ((const float4*)dl)[lane];
    float4 d1 = ((const float4*)dl)[lane + 32];
    a.x += d0.x; a.y += d0.y; a.z += d0.z; a.w += d0.w;
    b.x += d1.x; b.y += d1.y; b.z += d1.z; b.w += d1.w;

    float m = fmaxf(fmaxf(fmaxf(a.x, a.y), fmaxf(a.z, a.w)),
                    fmaxf(fmaxf(b.x, b.y), fmaxf(b.z, b.w)));
    #pragma unroll
    for (int off = 16; off; off >>= 1) m = fmaxf(m, __shfl_xor_sync(0xffffffffu, m, off));
    a.x = __expf(a.x - m); a.y = __expf(a.y - m); a.z = __expf(a.z - m); a.w = __expf(a.w - m);
    b.x = __expf(b.x - m); b.y = __expf(b.y - m); b.z = __expf(b.z - m); b.w = __expf(b.w - m);
    float s = a.x + a.y + a.z + a.w + b.x + b.y + b.z + b.w;
    #pragma unroll
    for (int off = 16; off; off >>= 1) s += __shfl_xor_sync(0xffffffffu, s, off);
    float inv = 1.0f / s;
    a.x = tfround(a.x * inv); a.y = tfround(a.y * inv);
    a.z = tfround(a.z * inv); a.w = tfround(a.w * inv);
    b.x = tfround(b.x * inv); b.y = tfround(b.y * inv);
    b.z = tfround(b.z * inv); b.w = tfround(b.w * inv);
    ((float4*)e)[lane] = a;
    ((float4*)e)[lane + 32] = b;
}

// =================================================================================
// AV (tf32, pre-rounded operands): Ot[n][c] = attn[n][:] . V[c][:]
// =================================================================================
__global__ __launch_bounds__(256, 2) void av_mma()
{
    extern __shared__ float sm[];
    int hb = blockIdx.z;
    const float* A = g_E + (size_t)hb * NN * NN;
    const float* V = g_V + (size_t)hb * CH * NN;
    int rbase = blockIdx.y * 128;   // n
    int cbase = blockIdx.x * 128;   // c
    int tid = threadIdx.x;

    float acc[4][4][4] = {};
    run_gemm_tf<false>(acc, sm, A + (size_t)rbase * NN, NN,
                       V + (size_t)cbase * NN, NN, 8, nullptr, 0, tid);

    int wm = (tid >> 5) & 1, wn = tid >> 6, lr = (tid & 31) >> 2, lc = tid & 3;
    float* dst = g_Ot + (size_t)hb * NN * CH;
    #pragma unroll
    for (int mf = 0; mf < 4; mf++) {
        #pragma unroll
        for (int nf = 0; nf < 4; nf++) {
            int c = cbase + wn * 32 + nf * 8 + lc * 2;
            #pragma unroll
            for (int rh = 0; rh < 2; rh++) {
                int n = rbase + wm * 64 + mf * 16 + lr + rh * 8;
                *(float2*)(dst + (size_t)n * CH + c) =
                    make_float2(acc[mf][nf][rh * 2 + 0], acc[mf][nf][rh * 2 + 1]);
            }
        }
    }
}

// =================================================================================
// fused msw gating + combine: one block per (b, n).
//   Stages the five Ot rows in smem, computes the 4 gating dots with a block
//   reduction, bn+sigmoid, then the weighted combine — g_Ot read exactly once.
// =================================================================================
__global__ __launch_bounds__(256) void mswcomb_kernel(
    const float* __restrict__ mswW, const float* __restrict__ gg,
    const float* __restrict__ bbt,  const float* __restrict__ mmn,
    const float* __restrict__ vvr)
{
    __shared__ float buf[NHEADS][CH];
    __shared__ float red[8][4];
    __shared__ float wsh[4];
    int n = blockIdx.x, b = blockIdx.y;
    int tid = threadIdx.x;

    #pragma unroll
    for (int hd = 0; hd < NHEADS; hd++) {
        const float* src = g_Ot + ((size_t)(hd * BATCH + b) * NN + n) * CH;
        buf[hd][tid]       = src[tid];
        buf[hd][tid + 256] = src[tid + 256];
    }
    __syncthreads();

    float a0 = 0.f, a1 = 0.f, a2 = 0.f, a3 = 0.f;
    #pragma unroll
    for (int hd = 0; hd < NHEADS; hd++) {
        const float* w = mswW + hd * CH;
        #pragma unroll
        for (int i = 0; i < 2; i++) {
            int c = tid + i * 256;
            float xv = buf[hd][c];
            a0 += xv * w[c];
            a1 += xv * w[2560 + c];
            a2 += xv * w[2 * 2560 + c];
            a3 += xv * w[3 * 2560 + c];
        }
    }
    #pragma unroll
    for (int off = 16; off; off >>= 1) {
        a0 += __shfl_xor_sync(0xffffffffu, a0, off);
        a1 += __shfl_xor_sync(0xffffffffu, a1, off);
        a2 += __shfl_xor_sync(0xffffffffu, a2, off);
        a3 += __shfl_xor_sync(0xffffffffu, a3, off);
    }
    int lane = tid & 31, warp = tid >> 5;
    if (lane == 0) {
        red[warp][0] = a0; red[warp][1] = a1; red[warp][2] = a2; red[warp][3] = a3;
    }
    __syncthreads();
    if (tid < 4) {
        float s = 0.f;
        #pragma unroll
        for (int wp = 0; wp < 8; wp++) s += red[wp][tid];
        float z = (s - mmn[tid]) * (gg[tid] * rsqrtf(vvr[tid] + BN_EPS)) + bbt[tid];
        wsh[tid] = 1.f / (1.f + __expf(-z));
    }
    __syncthreads();

    float w0 = wsh[0], w1 = wsh[1], w2 = wsh[2], w3 = wsh[3];
    float* dst = g_MS + ((size_t)b * NN + n) * CH;
    #pragma unroll
    for (int i = 0; i < 2; i++) {
        int c = tid + i * 256;
        float r = buf[4][c] + w0 * buf[0][c] + w1 * buf[1][c]
                + w2 * buf[2][c] + w3 * buf[3][c];
        dst[c] = tfround(r);
    }
}

// =================================================================================
// conv3x3 implicit GEMM (tf32, pre-rounded operands): D[o][n], K = 4608
// =================================================================================
__global__ __launch_bounds__(256, 2) void conv_mma()
{
    extern __shared__ float sm[];
    int b = blockIdx.z;
    int rbase = blockIdx.y * 128;   // o
    int cbase = blockIdx.x * 128;   // n
    const float* MSb = g_MS + (size_t)b * NN * CH;
    int tid = threadIdx.x;

    float acc[4][4][4] = {};
    run_gemm_tf<true>(acc, sm, g_Wp + (size_t)rbase * KCONV, KCONV,
                      nullptr, 0, 144, MSb, cbase, tid);

    int wm = (tid >> 5) & 1, wn = tid >> 6, lr = (tid & 31) >> 2, lc = tid & 3;
    float* dst = g_CV + (size_t)b * CH * NN;
    #pragma unroll
    for (int mf = 0; mf < 4; mf++) {
        #pragma unroll
        for (int nf = 0; nf < 4; nf++) {
            int n = cbase + wn * 32 + nf * 8 + lc * 2;
            #pragma unroll
            for (int rh = 0; rh < 2; rh++) {
                int o = rbase + wm * 64 + mf * 16 + lr + rh * 8;
                *(float2*)(dst + (size_t)o * NN + n) =
                    make_float2(acc[mf][nf][rh * 2 + 0], acc[mf][nf][rh * 2 + 1]);
            }
        }
    }
}

// =================================================================================
// final: out = relu(bn_top(relu(bn_fus(conv)) + x))
// =================================================================================
__global__ __launch_bounds__(256) void final_kernel(
    const float* __restrict__ x,
    const float* __restrict__ fg, const float* __restrict__ fb,
    const float* __restrict__ fm, const float* __restrict__ fv,
    const float* __restrict__ tg, const float* __restrict__ tb,
    const float* __restrict__ tm, const float* __restrict__ tv,
    float* __restrict__ out)
{
    int idx = blockIdx.x * 256 + threadIdx.x;
    int c = (idx >> 8) & 511;
    float t = g_CV[idx];
    t = (t - fm[c]) * (fg[c] * rsqrtf(fv[c] + BN_EPS)) + fb[c];
    t = fmaxf(t, 0.f);
    t += x[idx];
    t = (t - tm[c]) * (tg[c] * rsqrtf(tv[c] + BN_EPS)) + tb[c];
    out[idx] = fmaxf(t, 0.f);
}

// =================================================================================
extern "C" void kernel_launch(void* const* d_in, const int* in_sizes, int n_in,
                              void* d_out, int out_size)
{
    const float* x0   = (const float*)d_in[0];
    const float* x1   = (const float*)d_in[1];
    const float* x2   = (const float*)d_in[2];
    const float* x3   = (const float*)d_in[3];
    const float* x4   = (const float*)d_in[4];
    const float* qW   = (const float*)d_in[5];
    const float* qB   = (const float*)d_in[6];
    const float* kW   = (const float*)d_in[7];
    const float* kB   = (const float*)d_in[8];
    const float* vW   = (const float*)d_in[9];
    const float* vB   = (const float*)d_in[10];
    const float* relH = (const float*)d_in[11];
    const float* relW = (const float*)d_in[12];
    const float* mswW = (const float*)d_in[13];
    const float* mswg = (const float*)d_in[14];
    const float* mswb = (const float*)d_in[15];
    const float* mswm = (const float*)d_in[16];
    const float* mswv = (const float*)d_in[17];
    const float* fusW = (const float*)d_in[18];
    const float* fusg = (const float*)d_in[19];
    const float* fusb = (const float*)d_in[20];
    const float* fusm = (const float*)d_in[21];
    const float* fusv = (const float*)d_in[22];
    const float* topg = (const float*)d_in[23];
    const float* topb = (const float*)d_in[24];
    const float* topm = (const float*)d_in[25];
    const float* topv = (const float*)d_in[26];
    float* out = (float*)d_out;

    cudaFuncSetAttribute(m_mma,      cudaFuncAttributeMaxDynamicSharedMemorySize, SMEMB_BYTES);
    cudaFuncSetAttribute(kpp_mma,    cudaFuncAttributeMaxDynamicSharedMemorySize, SMEMB_BYTES);
    cudaFuncSetAttribute(v_mma,      cudaFuncAttributeMaxDynamicSharedMemorySize, SMEMB_BYTES);
    cudaFuncSetAttribute(energy_mma, cudaFuncAttributeMaxDynamicSharedMemorySize, SMEMB_BYTES);
    cudaFuncSetAttribute(av_mma,     cudaFuncAttributeMaxDynamicSharedMemorySize, SMEM_BYTES);
    cudaFuncSetAttribute(conv_mma,   cudaFuncAttributeMaxDynamicSharedMemorySize, SMEM_BYTES);

    transpose_kernel<<<dim3(8, 16, NHEADS * BATCH), dim3(32, 8)>>>(x0, x1, x2, x3, x4);
    wtrans_kernel<<<dim3(16, 16, 2 * NHEADS), dim3(32, 8)>>>(qW, kW);
    wsplit_kernel<<<NHEADS * CH * CH / 256, 256>>>(vW);
    permW_kernel<<<CH, 256>>>(fusW);

    // prep: M = Wq^T Wk, PH/PW, wt, dHW, delta
    m_mma<<<dim3(4, 4, NHEADS), 256, SMEMB_BYTES>>>();
    php_kernel<<<dim3(CH / 64, NHEADS), 256>>>(relH, relW);
    wt_kernel<<<dim3(CH / 8, NHEADS), 256>>>(qB);
    dhw_kernel<<<NHEADS, 256>>>(relH, relW, qB, kB);
    delta_kernel<<<dim3(NN / 8, NHEADS * BATCH), 256>>>();

    // K'' = Xt M^T + Pq
    kpp_mma<<<dim3(4, 2, NHEADS * BATCH), 256, SMEMB_BYTES>>>();

    // V projection
    v_mma<<<dim3(2, 4, NHEADS * BATCH), 256, SMEMB_BYTES>>>(vB);

    // energy = Xt . K''
    energy_mma<<<dim3(2, 2, NHEADS * BATCH), 256, SMEMB_BYTES>>>();

    softmax_kernel<<<(NHEADS * BATCH * NN) / 8, 256>>>();

    av_mma<<<dim3(4, 2, NHEADS * BATCH), 256, SMEM_BYTES>>>();

    // fused gating + combine
    mswcomb_kernel<<<dim3(NN, BATCH), 256>>>(mswW, mswg, mswb, mswm, mswv);

    conv_mma<<<dim3(2, 4, BATCH), 256, SMEM_BYTES>>>();

    final_kernel<<<(BATCH * CH * NN) / 256, 256>>>(
        x4, fusg, fusb, fusm, fusv, topg, topb, topm, topv, out);
}